// round 3
// baseline (speedup 1.0000x reference)
#include <cuda_runtime.h>
#include <math.h>

// Problem constants
#define Bsz   2
#define SEQ   2048
#define DIM   1024
#define NH    16
#define HD    64
#define TOKENS (Bsz*SEQ)     // 4096
#define QKVD   (3*DIM)       // 3072
#define NTILE  (SEQ/64)      // 32 key/query tiles of 64

// ---------------------------------------------------------------------------
// Scratch (device globals; no allocations allowed)
// ---------------------------------------------------------------------------
__device__ float g_qkv[TOKENS * QKVD];          // 50.3 MB  [b,n, t,h,d]
__device__ float g_q[Bsz * NH * SEQ * HD];      // 16.8 MB  [b,h,n,d] (pre-scaled)
__device__ float g_k[Bsz * NH * SEQ * HD];      // 16.8 MB
__device__ float g_v[Bsz * NH * SEQ * HD];      // 16.8 MB
__device__ float g_ao[TOKENS * DIM];            // 16.8 MB  [b,n,h,d] = [b,n,c]
__device__ int   g_mflag[NTILE * NTILE];        // per 64x64 mask tile: nonzero?

// ---------------------------------------------------------------------------
// Generic NT SGEMM: C[M,N] = A[M,K] * B[N,K]^T (+ bias[N])
// BM=BN=64, BK=32, 256 threads, 4x4 micro-tile per thread.
// ---------------------------------------------------------------------------
#define GBM 64
#define GBN 64
#define GBK 32

__global__ __launch_bounds__(256)
void gemm_nt_kernel(const float* __restrict__ A, const float* __restrict__ B,
                    float* __restrict__ C, int M, int Nn, int K,
                    const float* __restrict__ bias) {
    __shared__ float As[GBK][GBM + 1];
    __shared__ float Bs[GBK][GBN + 1];

    const int tid = threadIdx.x;
    const int tx  = tid & 15;      // 0..15 -> N micro
    const int ty  = tid >> 4;      // 0..15 -> M micro
    const int bm  = blockIdx.y * GBM;
    const int bn  = blockIdx.x * GBN;

    const int lrow  = tid >> 3;          // 0..31
    const int lcol4 = (tid & 7) << 2;    // 0,4,...,28

    float acc[4][4] = {};

    for (int k0 = 0; k0 < K; k0 += GBK) {
#pragma unroll
        for (int p = 0; p < 2; p++) {
            int r = lrow + p * 32;
            float4 av = *(const float4*)&A[(size_t)(bm + r) * K + k0 + lcol4];
            As[lcol4 + 0][r] = av.x; As[lcol4 + 1][r] = av.y;
            As[lcol4 + 2][r] = av.z; As[lcol4 + 3][r] = av.w;
            float4 bv = *(const float4*)&B[(size_t)(bn + r) * K + k0 + lcol4];
            Bs[lcol4 + 0][r] = bv.x; Bs[lcol4 + 1][r] = bv.y;
            Bs[lcol4 + 2][r] = bv.z; Bs[lcol4 + 3][r] = bv.w;
        }
        __syncthreads();

#pragma unroll
        for (int kk = 0; kk < GBK; kk++) {
            float a[4], b[4];
#pragma unroll
            for (int i = 0; i < 4; i++) a[i] = As[kk][ty * 4 + i];
#pragma unroll
            for (int j = 0; j < 4; j++) b[j] = Bs[kk][tx * 4 + j];
#pragma unroll
            for (int i = 0; i < 4; i++)
#pragma unroll
                for (int j = 0; j < 4; j++)
                    acc[i][j] += a[i] * b[j];
        }
        __syncthreads();
    }

    float bv[4] = {0.f, 0.f, 0.f, 0.f};
    if (bias) {
#pragma unroll
        for (int j = 0; j < 4; j++) bv[j] = bias[bn + tx * 4 + j];
    }
#pragma unroll
    for (int i = 0; i < 4; i++) {
        float4 ov;
        ov.x = acc[i][0] + bv[0];
        ov.y = acc[i][1] + bv[1];
        ov.z = acc[i][2] + bv[2];
        ov.w = acc[i][3] + bv[3];
        *(float4*)&C[(size_t)(bm + ty * 4 + i) * Nn + bn + tx * 4] = ov;
    }
}

// ---------------------------------------------------------------------------
// RMSNorm + RoPE + head split.  One warp per (b,n,h); 2 elems/lane (d, d+32).
// ---------------------------------------------------------------------------
__global__ __launch_bounds__(256)
void rmsrope_kernel(const float* __restrict__ fc, const float* __restrict__ fs,
                    const float* __restrict__ qg, const float* __restrict__ kg) {
    const int gw   = (blockIdx.x * blockDim.x + threadIdx.x) >> 5;
    const int lane = threadIdx.x & 31;
    // gw over Bsz*SEQ*NH = 65536, h fastest
    const int h = gw & (NH - 1);
    const int n = (gw >> 4) & (SEQ - 1);
    const int b = gw >> 15;

    const float* base = g_qkv + (size_t)(b * SEQ + n) * QKVD + h * HD;
    const int d0 = lane, d1 = lane + 32;

    const size_t fbase = (size_t)(b * SEQ + n) * HD;
    const float fc0 = fc[fbase + d0], fc1 = fc[fbase + d1];
    const float fs0 = fs[fbase + d0], fs1 = fs[fbase + d1];

    const size_t ob = ((size_t)(b * NH + h) * SEQ + n) * HD;
    const unsigned FULL = 0xffffffffu;

    // ---- Q ----
    {
        float v0 = base[d0], v1 = base[d1];
        float ss = v0 * v0 + v1 * v1;
#pragma unroll
        for (int o = 16; o >= 1; o >>= 1) ss += __shfl_xor_sync(FULL, ss, o);
        float sc = 8.0f / fmaxf(sqrtf(ss), 1e-12f);   // sqrt(HD)=8
        v0 = v0 * sc * qg[d0];
        v1 = v1 * sc * qg[d1];
        float p0 = __shfl_xor_sync(FULL, v0, 1);
        float p1 = __shfl_xor_sync(FULL, v1, 1);
        float r0 = (d0 & 1) ? p0 : -p0;
        float r1 = (d1 & 1) ? p1 : -p1;
        v0 = v0 * fc0 + r0 * fs0;
        v1 = v1 * fc1 + r1 * fs1;
        g_q[ob + d0] = v0 * 0.125f;                   // fold hd^-0.5
        g_q[ob + d1] = v1 * 0.125f;
    }
    // ---- K ----
    {
        float v0 = base[DIM + d0], v1 = base[DIM + d1];
        float ss = v0 * v0 + v1 * v1;
#pragma unroll
        for (int o = 16; o >= 1; o >>= 1) ss += __shfl_xor_sync(FULL, ss, o);
        float sc = 8.0f / fmaxf(sqrtf(ss), 1e-12f);
        v0 = v0 * sc * kg[d0];
        v1 = v1 * sc * kg[d1];
        float p0 = __shfl_xor_sync(FULL, v0, 1);
        float p1 = __shfl_xor_sync(FULL, v1, 1);
        float r0 = (d0 & 1) ? p0 : -p0;
        float r1 = (d1 & 1) ? p1 : -p1;
        g_k[ob + d0] = v0 * fc0 + r0 * fs0;
        g_k[ob + d1] = v1 * fc1 + r1 * fs1;
    }
    // ---- V (copy) ----
    g_v[ob + d0] = base[2 * DIM + d0];
    g_v[ob + d1] = base[2 * DIM + d1];
}

// ---------------------------------------------------------------------------
// Mask tile nonzero flags (1024 tiles of 64x64)
// ---------------------------------------------------------------------------
__global__ __launch_bounds__(256)
void maskflag_kernel(const float* __restrict__ mask) {
    const int qt = blockIdx.x >> 5;
    const int kt = blockIdx.x & 31;
    int nz = 0;
    for (int u = threadIdx.x; u < 64 * 16; u += 256) {     // float4 granules
        int r = u >> 4, c4 = (u & 15) << 2;
        float4 v = *(const float4*)&mask[(size_t)(qt * 64 + r) * SEQ + kt * 64 + c4];
        nz |= (v.x != 0.f) | (v.y != 0.f) | (v.z != 0.f) | (v.w != 0.f);
    }
    nz = __syncthreads_or(nz);
    if (threadIdx.x == 0) g_mflag[blockIdx.x] = nz;
}

// ---------------------------------------------------------------------------
// Flash attention: block = (qt, bh) handling 64 query rows, loop over 32
// key tiles of 64. 256 threads as 16x16, 4x4 micro-tiles.
// Dyn smem: Qs/Ks/Vs/Ps each 64x68 floats = 69632 B total.
// ---------------------------------------------------------------------------
#define FSTRIDE 68
#define FTILE   (64 * FSTRIDE)

__global__ __launch_bounds__(256)
void flash_kernel(const float* __restrict__ mask) {
    extern __shared__ float sm[];
    float* Qs = sm;
    float* Ks = sm + FTILE;
    float* Vs = sm + 2 * FTILE;
    float* Ps = sm + 3 * FTILE;

    const int qt  = blockIdx.x;          // 0..31
    const int bh  = blockIdx.y;          // 0..31
    const int tid = threadIdx.x;
    const int tx  = tid & 15;
    const int ty  = tid >> 4;
    const unsigned FULL = 0xffffffffu;

    const float* qb = g_q + (size_t)bh * SEQ * HD;
    const float* kb = g_k + (size_t)bh * SEQ * HD;
    const float* vb = g_v + (size_t)bh * SEQ * HD;

    // Load Q tile (pre-scaled)
    for (int u = tid; u < 64 * 16; u += 256) {
        int r = u >> 4, c4 = (u & 15) << 2;
        *(float4*)&Qs[r * FSTRIDE + c4] =
            *(const float4*)&qb[(size_t)(qt * 64 + r) * HD + c4];
    }

    float m_[4], l_[4], o_[4][4];
#pragma unroll
    for (int i = 0; i < 4; i++) {
        m_[i] = -INFINITY; l_[i] = 0.f;
#pragma unroll
        for (int j = 0; j < 4; j++) o_[i][j] = 0.f;
    }

    for (int kt = 0; kt < NTILE; kt++) {
        __syncthreads();   // previous PV done with Ks/Vs/Ps (also orders Q store)
        for (int u = tid; u < 64 * 16; u += 256) {
            int r = u >> 4, c4 = (u & 15) << 2;
            *(float4*)&Ks[r * FSTRIDE + c4] =
                *(const float4*)&kb[(size_t)(kt * 64 + r) * HD + c4];
            *(float4*)&Vs[r * FSTRIDE + c4] =
                *(const float4*)&vb[(size_t)(kt * 64 + r) * HD + c4];
        }
        const int mf = g_mflag[qt * NTILE + kt];
        if (mf) {
            for (int u = tid; u < 64 * 16; u += 256) {
                int r = u >> 4, c4 = (u & 15) << 2;
                *(float4*)&Ps[r * FSTRIDE + c4] =
                    *(const float4*)&mask[(size_t)(qt * 64 + r) * SEQ + kt * 64 + c4];
            }
        }
        __syncthreads();

        // S = Q * K^T (4x4 micro-tile)
        float s[4][4] = {};
#pragma unroll
        for (int d = 0; d < HD; d += 4) {
            float4 b0 = *(const float4*)&Ks[(4 * tx + 0) * FSTRIDE + d];
            float4 b1 = *(const float4*)&Ks[(4 * tx + 1) * FSTRIDE + d];
            float4 b2 = *(const float4*)&Ks[(4 * tx + 2) * FSTRIDE + d];
            float4 b3 = *(const float4*)&Ks[(4 * tx + 3) * FSTRIDE + d];
#pragma unroll
            for (int i = 0; i < 4; i++) {
                float4 a = *(const float4*)&Qs[(4 * ty + i) * FSTRIDE + d];
                s[i][0] += a.x * b0.x + a.y * b0.y + a.z * b0.z + a.w * b0.w;
                s[i][1] += a.x * b1.x + a.y * b1.y + a.z * b1.z + a.w * b1.w;
                s[i][2] += a.x * b2.x + a.y * b2.y + a.z * b2.z + a.w * b2.w;
                s[i][3] += a.x * b3.x + a.y * b3.y + a.z * b3.z + a.w * b3.w;
            }
        }
        if (mf) {
#pragma unroll
            for (int i = 0; i < 4; i++)
#pragma unroll
                for (int j = 0; j < 4; j++)
                    s[i][j] += Ps[(4 * ty + i) * FSTRIDE + 4 * tx + j];
        }

        // Online softmax (row groups = 16 lanes within half-warp)
#pragma unroll
        for (int i = 0; i < 4; i++) {
            float tm = fmaxf(fmaxf(s[i][0], s[i][1]), fmaxf(s[i][2], s[i][3]));
#pragma unroll
            for (int o = 1; o < 16; o <<= 1) tm = fmaxf(tm, __shfl_xor_sync(FULL, tm, o));
            float nm = fmaxf(m_[i], tm);
            float al = __expf(m_[i] - nm);
            float rs = 0.f;
#pragma unroll
            for (int j = 0; j < 4; j++) {
                float p = __expf(s[i][j] - nm);
                s[i][j] = p;
                rs += p;
            }
#pragma unroll
            for (int o = 1; o < 16; o <<= 1) rs += __shfl_xor_sync(FULL, rs, o);
            l_[i] = l_[i] * al + rs;
            m_[i] = nm;
#pragma unroll
            for (int j = 0; j < 4; j++) o_[i][j] *= al;
        }

        // store P
#pragma unroll
        for (int i = 0; i < 4; i++)
#pragma unroll
            for (int j = 0; j < 4; j++)
                Ps[(4 * ty + i) * FSTRIDE + 4 * tx + j] = s[i][j];
        __syncthreads();

        // O += P * V
#pragma unroll 4
        for (int c = 0; c < 64; c++) {
            float4 v4 = *(const float4*)&Vs[c * FSTRIDE + 4 * tx];
            float p0 = Ps[(4 * ty + 0) * FSTRIDE + c];
            float p1 = Ps[(4 * ty + 1) * FSTRIDE + c];
            float p2 = Ps[(4 * ty + 2) * FSTRIDE + c];
            float p3 = Ps[(4 * ty + 3) * FSTRIDE + c];
            o_[0][0] += p0 * v4.x; o_[0][1] += p0 * v4.y; o_[0][2] += p0 * v4.z; o_[0][3] += p0 * v4.w;
            o_[1][0] += p1 * v4.x; o_[1][1] += p1 * v4.y; o_[1][2] += p1 * v4.z; o_[1][3] += p1 * v4.w;
            o_[2][0] += p2 * v4.x; o_[2][1] += p2 * v4.y; o_[2][2] += p2 * v4.z; o_[2][3] += p2 * v4.w;
            o_[3][0] += p3 * v4.x; o_[3][1] += p3 * v4.y; o_[3][2] += p3 * v4.z; o_[3][3] += p3 * v4.w;
        }
    }

    // Epilogue: write [b,n,h,d]
    const int b = bh >> 4, h = bh & 15;
#pragma unroll
    for (int i = 0; i < 4; i++) {
        float inv = 1.f / l_[i];
        int n = qt * 64 + 4 * ty + i;
        float4 ov;
        ov.x = o_[i][0] * inv; ov.y = o_[i][1] * inv;
        ov.z = o_[i][2] * inv; ov.w = o_[i][3] * inv;
        *(float4*)&g_ao[(((size_t)(b * SEQ + n)) * NH + h) * HD + 4 * tx] = ov;
    }
}

// ---------------------------------------------------------------------------
// Launch
// ---------------------------------------------------------------------------
extern "C" void kernel_launch(void* const* d_in, const int* in_sizes, int n_in,
                              void* d_out, int out_size) {
    const float* x     = (const float*)d_in[0];
    const float* fc    = (const float*)d_in[1];
    const float* fs    = (const float*)d_in[2];
    const float* mask  = (const float*)d_in[3];
    const float* wqkv  = (const float*)d_in[4];
    const float* wproj = (const float*)d_in[5];
    const float* bproj = (const float*)d_in[6];
    const float* qg    = (const float*)d_in[7];
    const float* kg    = (const float*)d_in[8];
    float* out = (float*)d_out;

    float *qkvb, *aob;
    cudaGetSymbolAddress((void**)&qkvb, g_qkv);
    cudaGetSymbolAddress((void**)&aob, g_ao);

    // 1) QKV GEMM: [4096,3072] = x[4096,1024] * wqkv[3072,1024]^T
    {
        dim3 grid(QKVD / GBN, TOKENS / GBM);
        gemm_nt_kernel<<<grid, 256>>>(x, wqkv, qkvb, TOKENS, QKVD, DIM, nullptr);
    }
    // 2) RMSNorm + RoPE + split into [b,h,n,d]
    rmsrope_kernel<<<(Bsz * SEQ * NH) / 8, 256>>>(fc, fs, qg, kg);
    // 3) Mask tile flags
    maskflag_kernel<<<NTILE * NTILE, 256>>>(mask);
    // 4) Flash attention
    {
        size_t smem = 4 * FTILE * sizeof(float);
        cudaFuncSetAttribute(flash_kernel,
                             cudaFuncAttributeMaxDynamicSharedMemorySize, (int)smem);
        dim3 grid(NTILE, Bsz * NH);
        flash_kernel<<<grid, 256, smem>>>(mask);
    }
    // 5) Output projection: out[4096,1024] = ao * wproj^T + bproj
    {
        dim3 grid(DIM / GBN, TOKENS / GBM);
        gemm_nt_kernel<<<grid, 256>>>(aob, wproj, out, TOKENS, DIM, DIM, bproj);
    }
}

// round 8
// speedup vs baseline: 1.8475x; 1.8475x over previous
#include <cuda_runtime.h>
#include <math.h>
#include <stdint.h>

// Problem constants
#define Bsz   2
#define SEQ   2048
#define DIM   1024
#define NH    16
#define HD    64
#define TOKENS (Bsz*SEQ)     // 4096
#define QKVD   (3*DIM)       // 3072
#define NKT   (SEQ/64)       // 32 key tiles of 64
#define NQT   (SEQ/128)      // 16 query tiles of 128

// ---------------------------------------------------------------------------
// Scratch (device globals; no allocations allowed)
// ---------------------------------------------------------------------------
__device__ float g_qkv[TOKENS * QKVD];          // [b,n, t,h,d]
__device__ float g_q[Bsz * NH * SEQ * HD];      // [b,h,n,d] (pre-scaled)
__device__ float g_k[Bsz * NH * SEQ * HD];
__device__ float g_v[Bsz * NH * SEQ * HD];
__device__ float g_ao[TOKENS * DIM];            // [b,n,h,d] = [b,n,c]
__device__ int   g_mflag[NQT * NKT];            // per 128x64 mask tile: nonzero?

// ---------------------------------------------------------------------------
// tf32 helpers — 3xTF32 split for fp32-grade accuracy on tensor cores
// ---------------------------------------------------------------------------
__device__ __forceinline__ uint32_t f2tf32(float f) {
    uint32_t r;
    asm("cvt.rna.tf32.f32 %0, %1;" : "=r"(r) : "f"(f));
    return r;
}

__device__ __forceinline__ void split_tf32(float f, uint32_t& hi, uint32_t& lo) {
    hi = f2tf32(f);
    lo = f2tf32(f - __uint_as_float(hi));
}

__device__ __forceinline__ void mma_tf32(float4& d, const uint32_t a[4], const uint32_t b[2]) {
    asm volatile(
        "mma.sync.aligned.m16n8k8.row.col.f32.tf32.tf32.f32 "
        "{%0,%1,%2,%3}, {%4,%5,%6,%7}, {%8,%9}, {%0,%1,%2,%3};\n"
        : "+f"(d.x), "+f"(d.y), "+f"(d.z), "+f"(d.w)
        : "r"(a[0]), "r"(a[1]), "r"(a[2]), "r"(a[3]), "r"(b[0]), "r"(b[1]));
}

// D += A*B with split operands: hi*hi + lo*hi + hi*lo  (lo*lo dropped, ~2^-22)
__device__ __forceinline__ void mma3_tf32(float4& d,
                                          const uint32_t ah[4], const uint32_t al[4],
                                          const uint32_t bh[2], const uint32_t bl[2]) {
    mma_tf32(d, ah, bh);
    mma_tf32(d, al, bh);
    mma_tf32(d, ah, bl);
}

// ---------------------------------------------------------------------------
// 3xTF32 NT GEMM: C[M,N] = A[M,K] * B[N,K]^T (+ bias[N])
// BM=128, BN=64, BK=32; 256 threads = 8 warps (4 M x 2 N), warp tile 32x32.
// fp32 operands live in smem; hi/lo split happens at fragment load.
// ---------------------------------------------------------------------------
__global__ __launch_bounds__(256)
void gemm_tf32_nt(const float* __restrict__ A, const float* __restrict__ B,
                  float* __restrict__ C, int M, int Nn, int K,
                  const float* __restrict__ bias) {
    __shared__ float As[128][36];
    __shared__ float Bs[64][36];

    const int tid  = threadIdx.x;
    const int lane = tid & 31;
    const int w    = tid >> 5;
    const int wm   = w & 3;          // warp M index (0..3)
    const int wn   = w >> 2;         // warp N index (0..1)
    const int g    = lane >> 2;      // groupID 0..7
    const int t4   = lane & 3;       // threadID-in-group 0..3
    const int bm   = blockIdx.y * 128;
    const int bn   = blockIdx.x * 64;

    const int lr  = tid >> 3;        // 0..31
    const int lc4 = (tid & 7) << 2;  // 0..28

    float4 acc[2][4];
#pragma unroll
    for (int i = 0; i < 2; i++)
#pragma unroll
        for (int j = 0; j < 4; j++) acc[i][j] = make_float4(0.f, 0.f, 0.f, 0.f);

    for (int k0 = 0; k0 < K; k0 += 32) {
        __syncthreads();
#pragma unroll
        for (int p = 0; p < 4; p++) {
            int row = p * 32 + lr;
            *(float4*)&As[row][lc4] = *(const float4*)&A[(size_t)(bm + row) * K + k0 + lc4];
        }
#pragma unroll
        for (int p = 0; p < 2; p++) {
            int row = p * 32 + lr;
            *(float4*)&Bs[row][lc4] = *(const float4*)&B[(size_t)(bn + row) * K + k0 + lc4];
        }
        __syncthreads();

#pragma unroll
        for (int ks = 0; ks < 4; ks++) {
            const int ac = ks * 8 + t4;
            uint32_t ah[2][4], al[2][4], bh[4][2], bl[4][2];
#pragma unroll
            for (int mt = 0; mt < 2; mt++) {
                int ar = wm * 32 + mt * 16 + g;
                split_tf32(As[ar][ac],         ah[mt][0], al[mt][0]);
                split_tf32(As[ar + 8][ac],     ah[mt][1], al[mt][1]);
                split_tf32(As[ar][ac + 4],     ah[mt][2], al[mt][2]);
                split_tf32(As[ar + 8][ac + 4], ah[mt][3], al[mt][3]);
            }
#pragma unroll
            for (int nt = 0; nt < 4; nt++) {
                int br = wn * 32 + nt * 8 + g;
                split_tf32(Bs[br][ac],     bh[nt][0], bl[nt][0]);
                split_tf32(Bs[br][ac + 4], bh[nt][1], bl[nt][1]);
            }
#pragma unroll
            for (int mt = 0; mt < 2; mt++)
#pragma unroll
                for (int nt = 0; nt < 4; nt++)
                    mma3_tf32(acc[mt][nt], ah[mt], al[mt], bh[nt], bl[nt]);
        }
    }

#pragma unroll
    for (int mt = 0; mt < 2; mt++) {
#pragma unroll
        for (int nt = 0; nt < 4; nt++) {
            int row = bm + wm * 32 + mt * 16 + g;
            int col = bn + wn * 32 + nt * 8 + 2 * t4;
            float bx = 0.f, by = 0.f;
            if (bias) { bx = bias[col]; by = bias[col + 1]; }
            float2 o0 = make_float2(acc[mt][nt].x + bx, acc[mt][nt].y + by);
            float2 o1 = make_float2(acc[mt][nt].z + bx, acc[mt][nt].w + by);
            *(float2*)&C[(size_t)row * Nn + col] = o0;
            *(float2*)&C[(size_t)(row + 8) * Nn + col] = o1;
        }
    }
}

// ---------------------------------------------------------------------------
// RMSNorm + RoPE + head split.  One warp per (b,n,h); 2 elems/lane (d, d+32).
// ---------------------------------------------------------------------------
__global__ __launch_bounds__(256)
void rmsrope_kernel(const float* __restrict__ fc, const float* __restrict__ fs,
                    const float* __restrict__ qg, const float* __restrict__ kg) {
    const int gw   = (blockIdx.x * blockDim.x + threadIdx.x) >> 5;
    const int lane = threadIdx.x & 31;
    const int h = gw & (NH - 1);
    const int n = (gw >> 4) & (SEQ - 1);
    const int b = gw >> 15;

    const float* base = g_qkv + (size_t)(b * SEQ + n) * QKVD + h * HD;
    const int d0 = lane, d1 = lane + 32;

    const size_t fbase = (size_t)(b * SEQ + n) * HD;
    const float fc0 = fc[fbase + d0], fc1 = fc[fbase + d1];
    const float fs0 = fs[fbase + d0], fs1 = fs[fbase + d1];

    const size_t ob = ((size_t)(b * NH + h) * SEQ + n) * HD;
    const unsigned FULL = 0xffffffffu;

    // ---- Q ----
    {
        float v0 = base[d0], v1 = base[d1];
        float ss = v0 * v0 + v1 * v1;
#pragma unroll
        for (int o = 16; o >= 1; o >>= 1) ss += __shfl_xor_sync(FULL, ss, o);
        float sc = 8.0f / fmaxf(sqrtf(ss), 1e-12f);
        v0 = v0 * sc * qg[d0];
        v1 = v1 * sc * qg[d1];
        float p0 = __shfl_xor_sync(FULL, v0, 1);
        float p1 = __shfl_xor_sync(FULL, v1, 1);
        float r0 = (d0 & 1) ? p0 : -p0;
        float r1 = (d1 & 1) ? p1 : -p1;
        v0 = v0 * fc0 + r0 * fs0;
        v1 = v1 * fc1 + r1 * fs1;
        g_q[ob + d0] = v0 * 0.125f;
        g_q[ob + d1] = v1 * 0.125f;
    }
    // ---- K ----
    {
        float v0 = base[DIM + d0], v1 = base[DIM + d1];
        float ss = v0 * v0 + v1 * v1;
#pragma unroll
        for (int o = 16; o >= 1; o >>= 1) ss += __shfl_xor_sync(FULL, ss, o);
        float sc = 8.0f / fmaxf(sqrtf(ss), 1e-12f);
        v0 = v0 * sc * kg[d0];
        v1 = v1 * sc * kg[d1];
        float p0 = __shfl_xor_sync(FULL, v0, 1);
        float p1 = __shfl_xor_sync(FULL, v1, 1);
        float r0 = (d0 & 1) ? p0 : -p0;
        float r1 = (d1 & 1) ? p1 : -p1;
        g_k[ob + d0] = v0 * fc0 + r0 * fs0;
        g_k[ob + d1] = v1 * fc1 + r1 * fs1;
    }
    // ---- V (copy) ----
    g_v[ob + d0] = base[2 * DIM + d0];
    g_v[ob + d1] = base[2 * DIM + d1];
}

// ---------------------------------------------------------------------------
// Mask tile nonzero flags (16 x 32 tiles of 128x64)
// ---------------------------------------------------------------------------
__global__ __launch_bounds__(256)
void maskflag_kernel(const float* __restrict__ mask) {
    const int qt = blockIdx.x >> 5;
    const int kt = blockIdx.x & 31;
    int nz = 0;
    for (int u = threadIdx.x; u < 128 * 16; u += 256) {
        int r = u >> 4, c4 = (u & 15) << 2;
        float4 v = *(const float4*)&mask[(size_t)(qt * 128 + r) * SEQ + kt * 64 + c4];
        nz |= (v.x != 0.f) | (v.y != 0.f) | (v.z != 0.f) | (v.w != 0.f);
    }
    nz = __syncthreads_or(nz);
    if (threadIdx.x == 0) g_mflag[blockIdx.x] = nz;
}

// ---------------------------------------------------------------------------
// Flash attention with 3xTF32 tensor cores.
// Block = (qt, bh): 128 query rows, 8 warps x 16 rows each; loop 32 key tiles
// of 64.  Smem: Qs[128x68] Ks[64x68] Vs[64x68] Ps[128x68] = 104448 B (fp32).
// ---------------------------------------------------------------------------
#define FST 68
#define QS_OFF 0
#define KS_OFF (128*FST)
#define VS_OFF (KS_OFF + 64*FST)
#define PS_OFF (VS_OFF + 64*FST)
#define FLASH_SMEM ((PS_OFF + 128*FST) * 4)

__global__ __launch_bounds__(256)
void flash_tc_kernel(const float* __restrict__ mask) {
    extern __shared__ float sm[];
    float* Qs = sm + QS_OFF;
    float* Ks = sm + KS_OFF;
    float* Vs = sm + VS_OFF;
    float* Ps = sm + PS_OFF;

    const int qt   = blockIdx.x;    // 0..15
    const int bh   = blockIdx.y;    // 0..31
    const int tid  = threadIdx.x;
    const int lane = tid & 31;
    const int w    = tid >> 5;      // warp 0..7
    const int g    = lane >> 2;     // 0..7
    const int t4   = lane & 3;      // 0..3
    const unsigned FULL = 0xffffffffu;

    const float* qb = g_q + (size_t)bh * SEQ * HD;
    const float* kb = g_k + (size_t)bh * SEQ * HD;
    const float* vb = g_v + (size_t)bh * SEQ * HD;

    // Load Q tile (128x64), fp32
#pragma unroll
    for (int p = 0; p < 8; p++) {
        int u = tid + p * 256;
        int r = u >> 4, c4 = (u & 15) << 2;
        *(float4*)&Qs[r * FST + c4] =
            *(const float4*)&qb[(size_t)(qt * 128 + r) * HD + c4];
    }

    const int r0 = 16 * w + g;      // this thread's first q row (local)
    float m0 = -INFINITY, m1 = -INFINITY, l0 = 0.f, l1 = 0.f;
    float4 oacc[8];
#pragma unroll
    for (int dt = 0; dt < 8; dt++) oacc[dt] = make_float4(0.f, 0.f, 0.f, 0.f);

    for (int kt = 0; kt < NKT; kt++) {
        __syncthreads();   // prev PV done with Vs/Ps; also orders Qs first iter
#pragma unroll
        for (int p = 0; p < 4; p++) {
            int u = tid + p * 256;
            int r = u >> 4, c4 = (u & 15) << 2;
            *(float4*)&Ks[r * FST + c4] =
                *(const float4*)&kb[(size_t)(kt * 64 + r) * HD + c4];
            *(float4*)&Vs[r * FST + c4] =
                *(const float4*)&vb[(size_t)(kt * 64 + r) * HD + c4];
        }
        const int mf = g_mflag[qt * NKT + kt];
        if (mf) {
#pragma unroll
            for (int p = 0; p < 8; p++) {
                int u = tid + p * 256;
                int r = u >> 4, c4 = (u & 15) << 2;
                *(float4*)&Ps[r * FST + c4] =
                    *(const float4*)&mask[(size_t)(qt * 128 + r) * SEQ + kt * 64 + c4];
            }
        }
        __syncthreads();

        // S = Q K^T : per warp 16x64 via 3xTF32 m16n8k8
        float4 sacc[8];
#pragma unroll
        for (int nt = 0; nt < 8; nt++) sacc[nt] = make_float4(0.f, 0.f, 0.f, 0.f);
#pragma unroll
        for (int ks = 0; ks < 8; ks++) {
            const int ac = ks * 8 + t4;
            uint32_t ah[4], al[4];
            split_tf32(Qs[r0 * FST + ac],           ah[0], al[0]);
            split_tf32(Qs[(r0 + 8) * FST + ac],     ah[1], al[1]);
            split_tf32(Qs[r0 * FST + ac + 4],       ah[2], al[2]);
            split_tf32(Qs[(r0 + 8) * FST + ac + 4], ah[3], al[3]);
#pragma unroll
            for (int nt = 0; nt < 8; nt++) {
                uint32_t bh_[2], bl_[2];
                split_tf32(Ks[(nt * 8 + g) * FST + ac],     bh_[0], bl_[0]);
                split_tf32(Ks[(nt * 8 + g) * FST + ac + 4], bh_[1], bl_[1]);
                mma3_tf32(sacc[nt], ah, al, bh_, bl_);
            }
        }
        if (mf) {
#pragma unroll
            for (int nt = 0; nt < 8; nt++) {
                int c = nt * 8 + 2 * t4;
                sacc[nt].x += Ps[r0 * FST + c];
                sacc[nt].y += Ps[r0 * FST + c + 1];
                sacc[nt].z += Ps[(r0 + 8) * FST + c];
                sacc[nt].w += Ps[(r0 + 8) * FST + c + 1];
            }
        }

        // Online softmax: thread owns rows r0 (x,y) and r0+8 (z,w);
        // 4 lanes (same g) cover the 64 cols -> reduce over xor 1,2.
        float tm0 = -INFINITY, tm1 = -INFINITY;
#pragma unroll
        for (int nt = 0; nt < 8; nt++) {
            tm0 = fmaxf(tm0, fmaxf(sacc[nt].x, sacc[nt].y));
            tm1 = fmaxf(tm1, fmaxf(sacc[nt].z, sacc[nt].w));
        }
#pragma unroll
        for (int o = 1; o < 4; o <<= 1) {
            tm0 = fmaxf(tm0, __shfl_xor_sync(FULL, tm0, o));
            tm1 = fmaxf(tm1, __shfl_xor_sync(FULL, tm1, o));
        }
        float nm0 = fmaxf(m0, tm0), nm1 = fmaxf(m1, tm1);
        float al0 = __expf(m0 - nm0), al1 = __expf(m1 - nm1);
        float rs0 = 0.f, rs1 = 0.f;
#pragma unroll
        for (int nt = 0; nt < 8; nt++) {
            float px = __expf(sacc[nt].x - nm0);
            float py = __expf(sacc[nt].y - nm0);
            float pz = __expf(sacc[nt].z - nm1);
            float pw = __expf(sacc[nt].w - nm1);
            rs0 += px + py; rs1 += pz + pw;
            int c = nt * 8 + 2 * t4;
            Ps[r0 * FST + c]           = px;
            Ps[r0 * FST + c + 1]       = py;
            Ps[(r0 + 8) * FST + c]     = pz;
            Ps[(r0 + 8) * FST + c + 1] = pw;
        }
#pragma unroll
        for (int o = 1; o < 4; o <<= 1) {
            rs0 += __shfl_xor_sync(FULL, rs0, o);
            rs1 += __shfl_xor_sync(FULL, rs1, o);
        }
        l0 = l0 * al0 + rs0; m0 = nm0;
        l1 = l1 * al1 + rs1; m1 = nm1;
#pragma unroll
        for (int dt = 0; dt < 8; dt++) {
            oacc[dt].x *= al0; oacc[dt].y *= al0;
            oacc[dt].z *= al1; oacc[dt].w *= al1;
        }
        __syncwarp();

        // O += P V : per warp 16x64 via 3xTF32
#pragma unroll
        for (int ks = 0; ks < 8; ks++) {
            const int ac = ks * 8 + t4;
            uint32_t ah[4], al[4];
            split_tf32(Ps[r0 * FST + ac],           ah[0], al[0]);
            split_tf32(Ps[(r0 + 8) * FST + ac],     ah[1], al[1]);
            split_tf32(Ps[r0 * FST + ac + 4],       ah[2], al[2]);
            split_tf32(Ps[(r0 + 8) * FST + ac + 4], ah[3], al[3]);
#pragma unroll
            for (int dt = 0; dt < 8; dt++) {
                uint32_t bh_[2], bl_[2];
                split_tf32(Vs[(ks * 8 + t4) * FST + dt * 8 + g],     bh_[0], bl_[0]);
                split_tf32(Vs[(ks * 8 + t4 + 4) * FST + dt * 8 + g], bh_[1], bl_[1]);
                mma3_tf32(oacc[dt], ah, al, bh_, bl_);
            }
        }
    }

    // Epilogue: write [b,n,h,d]
    const int b = bh >> 4, h = bh & 15;
    const float inv0 = 1.f / l0, inv1 = 1.f / l1;
    const int n0 = qt * 128 + r0;
    const int n1 = n0 + 8;
#pragma unroll
    for (int dt = 0; dt < 8; dt++) {
        int d = dt * 8 + 2 * t4;
        float2 o0 = make_float2(oacc[dt].x * inv0, oacc[dt].y * inv0);
        float2 o1 = make_float2(oacc[dt].z * inv1, oacc[dt].w * inv1);
        *(float2*)&g_ao[(((size_t)(b * SEQ + n0)) * NH + h) * HD + d] = o0;
        *(float2*)&g_ao[(((size_t)(b * SEQ + n1)) * NH + h) * HD + d] = o1;
    }
}

// ---------------------------------------------------------------------------
// Launch
// ---------------------------------------------------------------------------
extern "C" void kernel_launch(void* const* d_in, const int* in_sizes, int n_in,
                              void* d_out, int out_size) {
    const float* x     = (const float*)d_in[0];
    const float* fc    = (const float*)d_in[1];
    const float* fs    = (const float*)d_in[2];
    const float* mask  = (const float*)d_in[3];
    const float* wqkv  = (const float*)d_in[4];
    const float* wproj = (const float*)d_in[5];
    const float* bproj = (const float*)d_in[6];
    const float* qg    = (const float*)d_in[7];
    const float* kg    = (const float*)d_in[8];
    float* out = (float*)d_out;

    float *qkvb, *aob;
    cudaGetSymbolAddress((void**)&qkvb, g_qkv);
    cudaGetSymbolAddress((void**)&aob, g_ao);

    // 1) QKV GEMM: [4096,3072] = x[4096,1024] * wqkv[3072,1024]^T
    {
        dim3 grid(QKVD / 64, TOKENS / 128);
        gemm_tf32_nt<<<grid, 256>>>(x, wqkv, qkvb, TOKENS, QKVD, DIM, nullptr);
    }
    // 2) RMSNorm + RoPE + split into [b,h,n,d]
    rmsrope_kernel<<<(Bsz * SEQ * NH) / 8, 256>>>(fc, fs, qg, kg);
    // 3) Mask tile flags (128x64 tiles)
    maskflag_kernel<<<NQT * NKT, 256>>>(mask);
    // 4) Flash attention (3xTF32 tensor cores)
    {
        cudaFuncSetAttribute(flash_tc_kernel,
                             cudaFuncAttributeMaxDynamicSharedMemorySize, FLASH_SMEM);
        dim3 grid(NQT, Bsz * NH);
        flash_tc_kernel<<<grid, 256, FLASH_SMEM>>>(mask);
    }
    // 5) Output projection: out[4096,1024] = ao * wproj^T + bproj
    {
        dim3 grid(DIM / 64, TOKENS / 128);
        gemm_tf32_nt<<<grid, 256>>>(aob, wproj, out, TOKENS, DIM, DIM, bproj);
    }
}

// round 13
// speedup vs baseline: 3.1926x; 1.7280x over previous
#include <cuda_runtime.h>
#include <cuda_bf16.h>
#include <math.h>
#include <stdint.h>

// Problem constants
#define Bsz   2
#define SEQ   2048
#define DIM   1024
#define NH    16
#define HD    64
#define TOKENS (Bsz*SEQ)     // 4096
#define QKVD   (3*DIM)       // 3072
#define NKT   (SEQ/64)       // 32 key tiles of 64
#define NQT   (SEQ/128)      // 16 query tiles of 128

// ---------------------------------------------------------------------------
// Scratch (device globals; no allocations allowed)
// ---------------------------------------------------------------------------
__device__ float g_qkv[TOKENS * QKVD];          // [b,n, t,h,d]
__device__ float g_q[Bsz * NH * SEQ * HD];      // [b,h,n,d] (pre-scaled)
__device__ float g_k[Bsz * NH * SEQ * HD];
__device__ float g_v[Bsz * NH * SEQ * HD];
__device__ float g_ao[TOKENS * DIM];            // [b,n,h,d] = [b,n,c]
__device__ int   g_mflag[NQT * NKT];            // per 128x64 mask tile: nonzero?

// ---------------------------------------------------------------------------
// bf16x3 helpers: x = hi + lo, each bf16; D += Ah*Bh + Al*Bh + Ah*Bl
// ---------------------------------------------------------------------------
__device__ __forceinline__ void bsplit2(float e0, float e1, uint32_t& hp, uint32_t& lp) {
    __nv_bfloat16 h0 = __float2bfloat16_rn(e0);
    __nv_bfloat16 h1 = __float2bfloat16_rn(e1);
    float r0 = e0 - __bfloat162float(h0);
    float r1 = e1 - __bfloat162float(h1);
    __nv_bfloat16 l0 = __float2bfloat16_rn(r0);
    __nv_bfloat16 l1 = __float2bfloat16_rn(r1);
    hp = (uint32_t)__bfloat16_as_ushort(h0) | ((uint32_t)__bfloat16_as_ushort(h1) << 16);
    lp = (uint32_t)__bfloat16_as_ushort(l0) | ((uint32_t)__bfloat16_as_ushort(l1) << 16);
}

__device__ __forceinline__ void bsplit1(float e, __nv_bfloat16& h, __nv_bfloat16& l) {
    h = __float2bfloat16_rn(e);
    l = __float2bfloat16_rn(e - __bfloat162float(h));
}

__device__ __forceinline__ void mma_bf16(float4& d, const uint32_t a[4], const uint32_t b[2]) {
    asm volatile(
        "mma.sync.aligned.m16n8k16.row.col.f32.bf16.bf16.f32 "
        "{%0,%1,%2,%3}, {%4,%5,%6,%7}, {%8,%9}, {%0,%1,%2,%3};\n"
        : "+f"(d.x), "+f"(d.y), "+f"(d.z), "+f"(d.w)
        : "r"(a[0]), "r"(a[1]), "r"(a[2]), "r"(a[3]), "r"(b[0]), "r"(b[1]));
}

__device__ __forceinline__ void mma3_bf16(float4& d,
                                          const uint32_t ah[4], const uint32_t al[4],
                                          const uint32_t bh[2], const uint32_t bl[2]) {
    mma_bf16(d, ah, bh);
    mma_bf16(d, al, bh);
    mma_bf16(d, ah, bl);
}

// u32 view of a bf16 smem location (index must be even)
#define U32AT(base, idx) (*(uint32_t*)((base) + (idx)))

// ---------------------------------------------------------------------------
// bf16x3 NT GEMM: C[M,N] = A[M,K] * B[N,K]^T (+ bias[N])
// BM=128, BN=64, BK=32; 256 threads = 8 warps (4 M x 2 N), warp tile 32x32.
// Split into hi/lo bf16 at smem-store time.
// ---------------------------------------------------------------------------
#define GST 40   // bf16 row stride for GEMM tiles

__global__ __launch_bounds__(256)
void gemm_bf16x3_nt(const float* __restrict__ A, const float* __restrict__ B,
                    float* __restrict__ C, int M, int Nn, int K,
                    const float* __restrict__ bias) {
    __shared__ __nv_bfloat16 Ash[128 * GST], Asl[128 * GST];
    __shared__ __nv_bfloat16 Bsh[64 * GST],  Bsl[64 * GST];

    const int tid  = threadIdx.x;
    const int lane = tid & 31;
    const int w    = tid >> 5;
    const int wm   = w & 3;          // warp M index (0..3)
    const int wn   = w >> 2;         // warp N index (0..1)
    const int g    = lane >> 2;      // 0..7
    const int t4   = lane & 3;       // 0..3
    const int bm   = blockIdx.y * 128;
    const int bn   = blockIdx.x * 64;

    const int lr  = tid >> 3;        // 0..31
    const int lc4 = (tid & 7) << 2;  // 0,4,...,28

    float4 acc[2][4];
#pragma unroll
    for (int i = 0; i < 2; i++)
#pragma unroll
        for (int j = 0; j < 4; j++) acc[i][j] = make_float4(0.f, 0.f, 0.f, 0.f);

    for (int k0 = 0; k0 < K; k0 += 32) {
        __syncthreads();
#pragma unroll
        for (int p = 0; p < 4; p++) {
            int row = p * 32 + lr;
            float4 v = *(const float4*)&A[(size_t)(bm + row) * K + k0 + lc4];
            uint32_t h0, l0, h1, l1;
            bsplit2(v.x, v.y, h0, l0);
            bsplit2(v.z, v.w, h1, l1);
            U32AT(Ash, row * GST + lc4)     = h0;
            U32AT(Ash, row * GST + lc4 + 2) = h1;
            U32AT(Asl, row * GST + lc4)     = l0;
            U32AT(Asl, row * GST + lc4 + 2) = l1;
        }
#pragma unroll
        for (int p = 0; p < 2; p++) {
            int row = p * 32 + lr;
            float4 v = *(const float4*)&B[(size_t)(bn + row) * K + k0 + lc4];
            uint32_t h0, l0, h1, l1;
            bsplit2(v.x, v.y, h0, l0);
            bsplit2(v.z, v.w, h1, l1);
            U32AT(Bsh, row * GST + lc4)     = h0;
            U32AT(Bsh, row * GST + lc4 + 2) = h1;
            U32AT(Bsl, row * GST + lc4)     = l0;
            U32AT(Bsl, row * GST + lc4 + 2) = l1;
        }
        __syncthreads();

#pragma unroll
        for (int ks = 0; ks < 2; ks++) {
            const int ac = ks * 16 + 2 * t4;
            uint32_t ah[2][4], al[2][4], bh[4][2], bl[4][2];
#pragma unroll
            for (int mt = 0; mt < 2; mt++) {
                int ar = wm * 32 + mt * 16 + g;
                ah[mt][0] = U32AT(Ash, ar * GST + ac);
                ah[mt][1] = U32AT(Ash, (ar + 8) * GST + ac);
                ah[mt][2] = U32AT(Ash, ar * GST + ac + 8);
                ah[mt][3] = U32AT(Ash, (ar + 8) * GST + ac + 8);
                al[mt][0] = U32AT(Asl, ar * GST + ac);
                al[mt][1] = U32AT(Asl, (ar + 8) * GST + ac);
                al[mt][2] = U32AT(Asl, ar * GST + ac + 8);
                al[mt][3] = U32AT(Asl, (ar + 8) * GST + ac + 8);
            }
#pragma unroll
            for (int nt = 0; nt < 4; nt++) {
                int br = wn * 32 + nt * 8 + g;
                bh[nt][0] = U32AT(Bsh, br * GST + ac);
                bh[nt][1] = U32AT(Bsh, br * GST + ac + 8);
                bl[nt][0] = U32AT(Bsl, br * GST + ac);
                bl[nt][1] = U32AT(Bsl, br * GST + ac + 8);
            }
#pragma unroll
            for (int mt = 0; mt < 2; mt++)
#pragma unroll
                for (int nt = 0; nt < 4; nt++)
                    mma3_bf16(acc[mt][nt], ah[mt], al[mt], bh[nt], bl[nt]);
        }
    }

#pragma unroll
    for (int mt = 0; mt < 2; mt++) {
#pragma unroll
        for (int nt = 0; nt < 4; nt++) {
            int row = bm + wm * 32 + mt * 16 + g;
            int col = bn + wn * 32 + nt * 8 + 2 * t4;
            float bx = 0.f, by = 0.f;
            if (bias) { bx = bias[col]; by = bias[col + 1]; }
            float2 o0 = make_float2(acc[mt][nt].x + bx, acc[mt][nt].y + by);
            float2 o1 = make_float2(acc[mt][nt].z + bx, acc[mt][nt].w + by);
            *(float2*)&C[(size_t)row * Nn + col] = o0;
            *(float2*)&C[(size_t)(row + 8) * Nn + col] = o1;
        }
    }
}

// ---------------------------------------------------------------------------
// RMSNorm + RoPE + head split.  One warp per (b,n,h); 2 elems/lane (d, d+32).
// ---------------------------------------------------------------------------
__global__ __launch_bounds__(256)
void rmsrope_kernel(const float* __restrict__ fc, const float* __restrict__ fs,
                    const float* __restrict__ qg, const float* __restrict__ kg) {
    const int gw   = (blockIdx.x * blockDim.x + threadIdx.x) >> 5;
    const int lane = threadIdx.x & 31;
    const int h = gw & (NH - 1);
    const int n = (gw >> 4) & (SEQ - 1);
    const int b = gw >> 15;

    const float* base = g_qkv + (size_t)(b * SEQ + n) * QKVD + h * HD;
    const int d0 = lane, d1 = lane + 32;

    const size_t fbase = (size_t)(b * SEQ + n) * HD;
    const float fc0 = fc[fbase + d0], fc1 = fc[fbase + d1];
    const float fs0 = fs[fbase + d0], fs1 = fs[fbase + d1];

    const size_t ob = ((size_t)(b * NH + h) * SEQ + n) * HD;
    const unsigned FULL = 0xffffffffu;

    // ---- Q ----
    {
        float v0 = base[d0], v1 = base[d1];
        float ss = v0 * v0 + v1 * v1;
#pragma unroll
        for (int o = 16; o >= 1; o >>= 1) ss += __shfl_xor_sync(FULL, ss, o);
        float sc = 8.0f / fmaxf(sqrtf(ss), 1e-12f);
        v0 = v0 * sc * qg[d0];
        v1 = v1 * sc * qg[d1];
        float p0 = __shfl_xor_sync(FULL, v0, 1);
        float p1 = __shfl_xor_sync(FULL, v1, 1);
        float r0 = (d0 & 1) ? p0 : -p0;
        float r1 = (d1 & 1) ? p1 : -p1;
        v0 = v0 * fc0 + r0 * fs0;
        v1 = v1 * fc1 + r1 * fs1;
        g_q[ob + d0] = v0 * 0.125f;
        g_q[ob + d1] = v1 * 0.125f;
    }
    // ---- K ----
    {
        float v0 = base[DIM + d0], v1 = base[DIM + d1];
        float ss = v0 * v0 + v1 * v1;
#pragma unroll
        for (int o = 16; o >= 1; o >>= 1) ss += __shfl_xor_sync(FULL, ss, o);
        float sc = 8.0f / fmaxf(sqrtf(ss), 1e-12f);
        v0 = v0 * sc * kg[d0];
        v1 = v1 * sc * kg[d1];
        float p0 = __shfl_xor_sync(FULL, v0, 1);
        float p1 = __shfl_xor_sync(FULL, v1, 1);
        float r0 = (d0 & 1) ? p0 : -p0;
        float r1 = (d1 & 1) ? p1 : -p1;
        g_k[ob + d0] = v0 * fc0 + r0 * fs0;
        g_k[ob + d1] = v1 * fc1 + r1 * fs1;
    }
    // ---- V (copy) ----
    g_v[ob + d0] = base[2 * DIM + d0];
    g_v[ob + d1] = base[2 * DIM + d1];
}

// ---------------------------------------------------------------------------
// Mask tile nonzero flags (16 x 32 tiles of 128x64)
// ---------------------------------------------------------------------------
__global__ __launch_bounds__(256)
void maskflag_kernel(const float* __restrict__ mask) {
    const int qt = blockIdx.x >> 5;
    const int kt = blockIdx.x & 31;
    int nz = 0;
    for (int u = threadIdx.x; u < 128 * 16; u += 256) {
        int r = u >> 4, c4 = (u & 15) << 2;
        float4 v = *(const float4*)&mask[(size_t)(qt * 128 + r) * SEQ + kt * 64 + c4];
        nz |= (v.x != 0.f) | (v.y != 0.f) | (v.z != 0.f) | (v.w != 0.f);
    }
    nz = __syncthreads_or(nz);
    if (threadIdx.x == 0) g_mflag[blockIdx.x] = nz;
}

// ---------------------------------------------------------------------------
// Flash attention with bf16x3 tensor cores (m16n8k16).
// Block = (qt, bh): 128 query rows, 8 warps x 16 rows each; 32 key tiles of 64.
// All operands split hi/lo bf16 at producer time. V stored transposed (Vt[d][k]).
// Smem (bf16, stride 72): Qh/Ql 128r, Kh/Kl 64r, Vth/Vtl 64r, Ph/Pl 128r
//   = 110592 B.
// ---------------------------------------------------------------------------
#define STR 72
#define QH_OFF 0
#define QL_OFF (QH_OFF + 128*STR)
#define KH_OFF (QL_OFF + 128*STR)
#define KL_OFF (KH_OFF + 64*STR)
#define VH_OFF (KL_OFF + 64*STR)
#define VL_OFF (VH_OFF + 64*STR)
#define PH_OFF (VL_OFF + 64*STR)
#define PL_OFF (PH_OFF + 128*STR)
#define FLASH_SMEM ((PL_OFF + 128*STR) * 2)

__global__ __launch_bounds__(256)
void flash_tc_kernel(const float* __restrict__ mask) {
    extern __shared__ __nv_bfloat16 smb[];
    __nv_bfloat16* Qh  = smb + QH_OFF;
    __nv_bfloat16* Ql  = smb + QL_OFF;
    __nv_bfloat16* Kh  = smb + KH_OFF;
    __nv_bfloat16* Kl  = smb + KL_OFF;
    __nv_bfloat16* Vth = smb + VH_OFF;
    __nv_bfloat16* Vtl = smb + VL_OFF;
    __nv_bfloat16* Ph  = smb + PH_OFF;
    __nv_bfloat16* Pl  = smb + PL_OFF;

    const int qt   = blockIdx.x;    // 0..15
    const int bh   = blockIdx.y;    // 0..31
    const int tid  = threadIdx.x;
    const int lane = tid & 31;
    const int w    = tid >> 5;      // warp 0..7
    const int g    = lane >> 2;     // 0..7
    const int t4   = lane & 3;      // 0..3
    const unsigned FULL = 0xffffffffu;

    const float* qb = g_q + (size_t)bh * SEQ * HD;
    const float* kb = g_k + (size_t)bh * SEQ * HD;
    const float* vb = g_v + (size_t)bh * SEQ * HD;

    // Load Q tile (128x64): split into hi/lo bf16
#pragma unroll
    for (int p = 0; p < 8; p++) {
        int u = tid + p * 256;
        int r = u >> 4, c4 = (u & 15) << 2;
        float4 v = *(const float4*)&qb[(size_t)(qt * 128 + r) * HD + c4];
        uint32_t h0, l0, h1, l1;
        bsplit2(v.x, v.y, h0, l0);
        bsplit2(v.z, v.w, h1, l1);
        U32AT(Qh, r * STR + c4)     = h0;
        U32AT(Qh, r * STR + c4 + 2) = h1;
        U32AT(Ql, r * STR + c4)     = l0;
        U32AT(Ql, r * STR + c4 + 2) = l1;
    }

    const int r0 = 16 * w + g;      // this thread's first q row (local)
    float m0 = -INFINITY, m1 = -INFINITY, l0s = 0.f, l1s = 0.f;
    float4 oacc[8];
#pragma unroll
    for (int dt = 0; dt < 8; dt++) oacc[dt] = make_float4(0.f, 0.f, 0.f, 0.f);

    for (int kt = 0; kt < NKT; kt++) {
        __syncthreads();   // prev iter done with Kh/Vt; first iter orders Qh
#pragma unroll
        for (int p = 0; p < 4; p++) {
            int u = tid + p * 256;
            int r = u >> 4, c4 = (u & 15) << 2;           // r = key row, c4 = d
            float4 kv = *(const float4*)&kb[(size_t)(kt * 64 + r) * HD + c4];
            uint32_t h0, l0, h1, l1;
            bsplit2(kv.x, kv.y, h0, l0);
            bsplit2(kv.z, kv.w, h1, l1);
            U32AT(Kh, r * STR + c4)     = h0;
            U32AT(Kh, r * STR + c4 + 2) = h1;
            U32AT(Kl, r * STR + c4)     = l0;
            U32AT(Kl, r * STR + c4 + 2) = l1;
            float4 vv = *(const float4*)&vb[(size_t)(kt * 64 + r) * HD + c4];
            __nv_bfloat16 vh, vl;
            bsplit1(vv.x, vh, vl); Vth[(c4+0) * STR + r] = vh; Vtl[(c4+0) * STR + r] = vl;
            bsplit1(vv.y, vh, vl); Vth[(c4+1) * STR + r] = vh; Vtl[(c4+1) * STR + r] = vl;
            bsplit1(vv.z, vh, vl); Vth[(c4+2) * STR + r] = vh; Vtl[(c4+2) * STR + r] = vl;
            bsplit1(vv.w, vh, vl); Vth[(c4+3) * STR + r] = vh; Vtl[(c4+3) * STR + r] = vl;
        }
        __syncthreads();

        // S = Q K^T : per warp 16x64 via bf16x3 m16n8k16 (4 k-steps over HD=64)
        float4 sacc[8];
#pragma unroll
        for (int nt = 0; nt < 8; nt++) sacc[nt] = make_float4(0.f, 0.f, 0.f, 0.f);
#pragma unroll
        for (int ks = 0; ks < 4; ks++) {
            const int ac = ks * 16 + 2 * t4;
            uint32_t ah[4], al[4];
            ah[0] = U32AT(Qh, r0 * STR + ac);
            ah[1] = U32AT(Qh, (r0 + 8) * STR + ac);
            ah[2] = U32AT(Qh, r0 * STR + ac + 8);
            ah[3] = U32AT(Qh, (r0 + 8) * STR + ac + 8);
            al[0] = U32AT(Ql, r0 * STR + ac);
            al[1] = U32AT(Ql, (r0 + 8) * STR + ac);
            al[2] = U32AT(Ql, r0 * STR + ac + 8);
            al[3] = U32AT(Ql, (r0 + 8) * STR + ac + 8);
#pragma unroll
            for (int nt = 0; nt < 8; nt++) {
                int n = nt * 8 + g;
                uint32_t bh_[2], bl_[2];
                bh_[0] = U32AT(Kh, n * STR + ac);
                bh_[1] = U32AT(Kh, n * STR + ac + 8);
                bl_[0] = U32AT(Kl, n * STR + ac);
                bl_[1] = U32AT(Kl, n * STR + ac + 8);
                mma3_bf16(sacc[nt], ah, al, bh_, bl_);
            }
        }
        const int mf = g_mflag[qt * NKT + kt];
        if (mf) {
            const float* mr0 = mask + (size_t)(qt * 128 + r0) * SEQ + kt * 64;
            const float* mr1 = mr0 + 8 * SEQ;
#pragma unroll
            for (int nt = 0; nt < 8; nt++) {
                int c = nt * 8 + 2 * t4;
                float2 a0 = *(const float2*)&mr0[c];
                float2 a1 = *(const float2*)&mr1[c];
                sacc[nt].x += a0.x; sacc[nt].y += a0.y;
                sacc[nt].z += a1.x; sacc[nt].w += a1.y;
            }
        }

        // Online softmax: rows r0 (x,y) and r0+8 (z,w); reduce across 4 lanes.
        float tm0 = -INFINITY, tm1 = -INFINITY;
#pragma unroll
        for (int nt = 0; nt < 8; nt++) {
            tm0 = fmaxf(tm0, fmaxf(sacc[nt].x, sacc[nt].y));
            tm1 = fmaxf(tm1, fmaxf(sacc[nt].z, sacc[nt].w));
        }
#pragma unroll
        for (int o = 1; o < 4; o <<= 1) {
            tm0 = fmaxf(tm0, __shfl_xor_sync(FULL, tm0, o));
            tm1 = fmaxf(tm1, __shfl_xor_sync(FULL, tm1, o));
        }
        float nm0 = fmaxf(m0, tm0), nm1 = fmaxf(m1, tm1);
        float al0 = __expf(m0 - nm0), al1 = __expf(m1 - nm1);
        float rs0 = 0.f, rs1 = 0.f;
#pragma unroll
        for (int nt = 0; nt < 8; nt++) {
            float px = __expf(sacc[nt].x - nm0);
            float py = __expf(sacc[nt].y - nm0);
            float pz = __expf(sacc[nt].z - nm1);
            float pw = __expf(sacc[nt].w - nm1);
            rs0 += px + py; rs1 += pz + pw;
            int c = nt * 8 + 2 * t4;               // adjacent col pair
            uint32_t hp, lp;
            bsplit2(px, py, hp, lp);
            U32AT(Ph, r0 * STR + c) = hp;
            U32AT(Pl, r0 * STR + c) = lp;
            bsplit2(pz, pw, hp, lp);
            U32AT(Ph, (r0 + 8) * STR + c) = hp;
            U32AT(Pl, (r0 + 8) * STR + c) = lp;
        }
#pragma unroll
        for (int o = 1; o < 4; o <<= 1) {
            rs0 += __shfl_xor_sync(FULL, rs0, o);
            rs1 += __shfl_xor_sync(FULL, rs1, o);
        }
        l0s = l0s * al0 + rs0; m0 = nm0;
        l1s = l1s * al1 + rs1; m1 = nm1;
#pragma unroll
        for (int dt = 0; dt < 8; dt++) {
            oacc[dt].x *= al0; oacc[dt].y *= al0;
            oacc[dt].z *= al1; oacc[dt].w *= al1;
        }
        __syncwarp();   // P rows are warp-private; order stores vs frag loads

        // O += P V : per warp 16x64 via bf16x3 (4 k-steps over key dim 64)
#pragma unroll
        for (int ks = 0; ks < 4; ks++) {
            const int ac = ks * 16 + 2 * t4;
            uint32_t ah[4], al[4];
            ah[0] = U32AT(Ph, r0 * STR + ac);
            ah[1] = U32AT(Ph, (r0 + 8) * STR + ac);
            ah[2] = U32AT(Ph, r0 * STR + ac + 8);
            ah[3] = U32AT(Ph, (r0 + 8) * STR + ac + 8);
            al[0] = U32AT(Pl, r0 * STR + ac);
            al[1] = U32AT(Pl, (r0 + 8) * STR + ac);
            al[2] = U32AT(Pl, r0 * STR + ac + 8);
            al[3] = U32AT(Pl, (r0 + 8) * STR + ac + 8);
#pragma unroll
            for (int dt = 0; dt < 8; dt++) {
                int d = dt * 8 + g;
                uint32_t bh_[2], bl_[2];
                bh_[0] = U32AT(Vth, d * STR + ac);
                bh_[1] = U32AT(Vth, d * STR + ac + 8);
                bl_[0] = U32AT(Vtl, d * STR + ac);
                bl_[1] = U32AT(Vtl, d * STR + ac + 8);
                mma3_bf16(oacc[dt], ah, al, bh_, bl_);
            }
        }
    }

    // Epilogue: write [b,n,h,d]
    const int b = bh >> 4, h = bh & 15;
    const float inv0 = 1.f / l0s, inv1 = 1.f / l1s;
    const int n0 = qt * 128 + r0;
    const int n1 = n0 + 8;
#pragma unroll
    for (int dt = 0; dt < 8; dt++) {
        int d = dt * 8 + 2 * t4;
        float2 o0 = make_float2(oacc[dt].x * inv0, oacc[dt].y * inv0);
        float2 o1 = make_float2(oacc[dt].z * inv1, oacc[dt].w * inv1);
        *(float2*)&g_ao[(((size_t)(b * SEQ + n0)) * NH + h) * HD + d] = o0;
        *(float2*)&g_ao[(((size_t)(b * SEQ + n1)) * NH + h) * HD + d] = o1;
    }
}

// ---------------------------------------------------------------------------
// Launch
// ---------------------------------------------------------------------------
extern "C" void kernel_launch(void* const* d_in, const int* in_sizes, int n_in,
                              void* d_out, int out_size) {
    const float* x     = (const float*)d_in[0];
    const float* fc    = (const float*)d_in[1];
    const float* fs    = (const float*)d_in[2];
    const float* mask  = (const float*)d_in[3];
    const float* wqkv  = (const float*)d_in[4];
    const float* wproj = (const float*)d_in[5];
    const float* bproj = (const float*)d_in[6];
    const float* qg    = (const float*)d_in[7];
    const float* kg    = (const float*)d_in[8];
    float* out = (float*)d_out;

    float *qkvb, *aob;
    cudaGetSymbolAddress((void**)&qkvb, g_qkv);
    cudaGetSymbolAddress((void**)&aob, g_ao);

    // 1) QKV GEMM: [4096,3072] = x[4096,1024] * wqkv[3072,1024]^T
    {
        dim3 grid(QKVD / 64, TOKENS / 128);
        gemm_bf16x3_nt<<<grid, 256>>>(x, wqkv, qkvb, TOKENS, QKVD, DIM, nullptr);
    }
    // 2) RMSNorm + RoPE + split into [b,h,n,d]
    rmsrope_kernel<<<(Bsz * SEQ * NH) / 8, 256>>>(fc, fs, qg, kg);
    // 3) Mask tile flags (128x64 tiles)
    maskflag_kernel<<<NQT * NKT, 256>>>(mask);
    // 4) Flash attention (bf16x3 tensor cores)
    {
        cudaFuncSetAttribute(flash_tc_kernel,
                             cudaFuncAttributeMaxDynamicSharedMemorySize, FLASH_SMEM);
        dim3 grid(NQT, Bsz * NH);
        flash_tc_kernel<<<grid, 256, FLASH_SMEM>>>(mask);
    }
    // 5) Output projection: out[4096,1024] = ao * wproj^T + bproj
    {
        dim3 grid(DIM / 64, TOKENS / 128);
        gemm_bf16x3_nt<<<grid, 256>>>(aob, wproj, out, TOKENS, DIM, DIM, bproj);
    }
}

// round 14
// speedup vs baseline: 3.7218x; 1.1658x over previous
#include <cuda_runtime.h>
#include <cuda_bf16.h>
#include <math.h>
#include <stdint.h>

// Problem constants
#define Bsz   2
#define SEQ   2048
#define DIM   1024
#define NH    16
#define HD    64
#define TOKENS (Bsz*SEQ)     // 4096
#define QKVD   (3*DIM)       // 3072
#define NKT   (SEQ/64)       // 32 key tiles of 64
#define NQT   (SEQ/128)      // 16 query tiles of 128

// ---------------------------------------------------------------------------
// Scratch (device globals; no allocations allowed)
// ---------------------------------------------------------------------------
__device__ float g_qkv[TOKENS * QKVD];          // [b,n, t,h,d]
__device__ float g_q[Bsz * NH * SEQ * HD];      // [b,h,n,d] (pre-scaled)
__device__ float g_k[Bsz * NH * SEQ * HD];
__device__ float g_v[Bsz * NH * SEQ * HD];
__device__ float g_ao[TOKENS * DIM];            // [b,n,h,d] = [b,n,c]
__device__ int   g_mflag[NQT * NKT];            // per 128x64 mask tile: nonzero?

// ---------------------------------------------------------------------------
// bf16x3 helpers: x = hi + lo, each bf16; D += Ah*Bh + Al*Bh + Ah*Bl
// ---------------------------------------------------------------------------
__device__ __forceinline__ void bsplit2(float e0, float e1, uint32_t& hp, uint32_t& lp) {
    __nv_bfloat16 h0 = __float2bfloat16_rn(e0);
    __nv_bfloat16 h1 = __float2bfloat16_rn(e1);
    float r0 = e0 - __bfloat162float(h0);
    float r1 = e1 - __bfloat162float(h1);
    __nv_bfloat16 l0 = __float2bfloat16_rn(r0);
    __nv_bfloat16 l1 = __float2bfloat16_rn(r1);
    hp = (uint32_t)__bfloat16_as_ushort(h0) | ((uint32_t)__bfloat16_as_ushort(h1) << 16);
    lp = (uint32_t)__bfloat16_as_ushort(l0) | ((uint32_t)__bfloat16_as_ushort(l1) << 16);
}

__device__ __forceinline__ void mma_bf16(float4& d, const uint32_t a[4], const uint32_t b[2]) {
    asm volatile(
        "mma.sync.aligned.m16n8k16.row.col.f32.bf16.bf16.f32 "
        "{%0,%1,%2,%3}, {%4,%5,%6,%7}, {%8,%9}, {%0,%1,%2,%3};\n"
        : "+f"(d.x), "+f"(d.y), "+f"(d.z), "+f"(d.w)
        : "r"(a[0]), "r"(a[1]), "r"(a[2]), "r"(a[3]), "r"(b[0]), "r"(b[1]));
}

__device__ __forceinline__ void mma3_bf16(float4& d,
                                          const uint32_t ah[4], const uint32_t al[4],
                                          const uint32_t bh[2], const uint32_t bl[2]) {
    mma_bf16(d, ah, bh);
    mma_bf16(d, al, bh);
    mma_bf16(d, ah, bl);
}

__device__ __forceinline__ void ldsm4(uint32_t r[4], uint32_t a) {
    asm volatile("ldmatrix.sync.aligned.m8n8.x4.shared.b16 {%0,%1,%2,%3}, [%4];"
                 : "=r"(r[0]), "=r"(r[1]), "=r"(r[2]), "=r"(r[3]) : "r"(a));
}
__device__ __forceinline__ void ldsm4t(uint32_t r[4], uint32_t a) {
    asm volatile("ldmatrix.sync.aligned.m8n8.x4.trans.shared.b16 {%0,%1,%2,%3}, [%4];"
                 : "=r"(r[0]), "=r"(r[1]), "=r"(r[2]), "=r"(r[3]) : "r"(a));
}

// A-fragment (16x16) address: rows row0..+15 (lane&15), col ac + (lane>>4)*8
#define AADDR(base_b, row0, stride, ac, lane) \
    ((base_b) + ((((row0) + ((lane) & 15)) * (stride) + (ac) + (((lane) >> 4) << 3)) << 1))
// B-fragment pair (two n8k16 tiles at n0, n0+8): rows n, k-halves interleaved
#define BADDR(base_b, n0, stride, ac, lane) \
    ((base_b) + ((((n0) + (((lane) >> 4) << 3) + ((lane) & 7)) * (stride) + (ac) + ((((lane) >> 3) & 1) << 3)) << 1))
// Transposed B-fragment pair from natural [k][d] layout: rows k, cols d0/d0+8
#define BTADDR(base_b, d0, stride, ac, lane) \
    ((base_b) + ((((ac) + ((((lane) >> 3) & 1) << 3) + ((lane) & 7)) * (stride) + (d0) + (((lane) >> 4) << 3)) << 1))

// u32 view of a bf16 smem location (index must be even)
#define U32AT(base, idx) (*(uint32_t*)((base) + (idx)))

// ---------------------------------------------------------------------------
// bf16x3 NT GEMM: C[M,N] = A[M,K] * B[N,K]^T (+ bias[N])
// BM=128, BN=64, BK=32; 256 threads = 8 warps (4 M x 2 N), warp tile 32x32.
// Split into hi/lo bf16 at smem-store time; ldmatrix fragment loads.
// ---------------------------------------------------------------------------
#define GST 40   // bf16 row stride for GEMM tiles

__global__ __launch_bounds__(256)
void gemm_bf16x3_nt(const float* __restrict__ A, const float* __restrict__ B,
                    float* __restrict__ C, int M, int Nn, int K,
                    const float* __restrict__ bias) {
    __shared__ __align__(16) __nv_bfloat16 Ash[128 * GST], Asl[128 * GST];
    __shared__ __align__(16) __nv_bfloat16 Bsh[64 * GST],  Bsl[64 * GST];

    const int tid  = threadIdx.x;
    const int lane = tid & 31;
    const int w    = tid >> 5;
    const int wm   = w & 3;          // warp M index (0..3)
    const int wn   = w >> 2;         // warp N index (0..1)
    const int g    = lane >> 2;      // 0..7
    const int t4   = lane & 3;       // 0..3
    const int bm   = blockIdx.y * 128;
    const int bn   = blockIdx.x * 64;

    const uint32_t ash_b = (uint32_t)__cvta_generic_to_shared(Ash);
    const uint32_t asl_b = (uint32_t)__cvta_generic_to_shared(Asl);
    const uint32_t bsh_b = (uint32_t)__cvta_generic_to_shared(Bsh);
    const uint32_t bsl_b = (uint32_t)__cvta_generic_to_shared(Bsl);

    const int lr  = tid >> 3;        // 0..31
    const int lc4 = (tid & 7) << 2;  // 0,4,...,28

    float4 acc[2][4];
#pragma unroll
    for (int i = 0; i < 2; i++)
#pragma unroll
        for (int j = 0; j < 4; j++) acc[i][j] = make_float4(0.f, 0.f, 0.f, 0.f);

    for (int k0 = 0; k0 < K; k0 += 32) {
        __syncthreads();
#pragma unroll
        for (int p = 0; p < 4; p++) {
            int row = p * 32 + lr;
            float4 v = *(const float4*)&A[(size_t)(bm + row) * K + k0 + lc4];
            uint32_t h0, l0, h1, l1;
            bsplit2(v.x, v.y, h0, l0);
            bsplit2(v.z, v.w, h1, l1);
            U32AT(Ash, row * GST + lc4)     = h0;
            U32AT(Ash, row * GST + lc4 + 2) = h1;
            U32AT(Asl, row * GST + lc4)     = l0;
            U32AT(Asl, row * GST + lc4 + 2) = l1;
        }
#pragma unroll
        for (int p = 0; p < 2; p++) {
            int row = p * 32 + lr;
            float4 v = *(const float4*)&B[(size_t)(bn + row) * K + k0 + lc4];
            uint32_t h0, l0, h1, l1;
            bsplit2(v.x, v.y, h0, l0);
            bsplit2(v.z, v.w, h1, l1);
            U32AT(Bsh, row * GST + lc4)     = h0;
            U32AT(Bsh, row * GST + lc4 + 2) = h1;
            U32AT(Bsl, row * GST + lc4)     = l0;
            U32AT(Bsl, row * GST + lc4 + 2) = l1;
        }
        __syncthreads();

#pragma unroll
        for (int ks = 0; ks < 2; ks++) {
            const int ac = ks * 16;
            uint32_t ah[2][4], al[2][4];
#pragma unroll
            for (int mt = 0; mt < 2; mt++) {
                int ar = wm * 32 + mt * 16;
                ldsm4(ah[mt], AADDR(ash_b, ar, GST, ac, lane));
                ldsm4(al[mt], AADDR(asl_b, ar, GST, ac, lane));
            }
#pragma unroll
            for (int ntp = 0; ntp < 2; ntp++) {
                int n0 = wn * 32 + ntp * 16;
                uint32_t bh4[4], bl4[4];
                ldsm4(bh4, BADDR(bsh_b, n0, GST, ac, lane));
                ldsm4(bl4, BADDR(bsl_b, n0, GST, ac, lane));
#pragma unroll
                for (int mt = 0; mt < 2; mt++) {
                    mma3_bf16(acc[mt][2 * ntp],     ah[mt], al[mt], bh4,     bl4);
                    mma3_bf16(acc[mt][2 * ntp + 1], ah[mt], al[mt], bh4 + 2, bl4 + 2);
                }
            }
        }
    }

#pragma unroll
    for (int mt = 0; mt < 2; mt++) {
#pragma unroll
        for (int nt = 0; nt < 4; nt++) {
            int row = bm + wm * 32 + mt * 16 + g;
            int col = bn + wn * 32 + nt * 8 + 2 * t4;
            float bx = 0.f, by = 0.f;
            if (bias) { bx = bias[col]; by = bias[col + 1]; }
            float2 o0 = make_float2(acc[mt][nt].x + bx, acc[mt][nt].y + by);
            float2 o1 = make_float2(acc[mt][nt].z + bx, acc[mt][nt].w + by);
            *(float2*)&C[(size_t)row * Nn + col] = o0;
            *(float2*)&C[(size_t)(row + 8) * Nn + col] = o1;
        }
    }
}

// ---------------------------------------------------------------------------
// RMSNorm + RoPE + head split.  One warp per (b,n,h); 2 elems/lane (d, d+32).
// ---------------------------------------------------------------------------
__global__ __launch_bounds__(256)
void rmsrope_kernel(const float* __restrict__ fc, const float* __restrict__ fs,
                    const float* __restrict__ qg, const float* __restrict__ kg) {
    const int gw   = (blockIdx.x * blockDim.x + threadIdx.x) >> 5;
    const int lane = threadIdx.x & 31;
    const int h = gw & (NH - 1);
    const int n = (gw >> 4) & (SEQ - 1);
    const int b = gw >> 15;

    const float* base = g_qkv + (size_t)(b * SEQ + n) * QKVD + h * HD;
    const int d0 = lane, d1 = lane + 32;

    const size_t fbase = (size_t)(b * SEQ + n) * HD;
    const float fc0 = fc[fbase + d0], fc1 = fc[fbase + d1];
    const float fs0 = fs[fbase + d0], fs1 = fs[fbase + d1];

    const size_t ob = ((size_t)(b * NH + h) * SEQ + n) * HD;
    const unsigned FULL = 0xffffffffu;

    // ---- Q ----
    {
        float v0 = base[d0], v1 = base[d1];
        float ss = v0 * v0 + v1 * v1;
#pragma unroll
        for (int o = 16; o >= 1; o >>= 1) ss += __shfl_xor_sync(FULL, ss, o);
        float sc = 8.0f / fmaxf(sqrtf(ss), 1e-12f);
        v0 = v0 * sc * qg[d0];
        v1 = v1 * sc * qg[d1];
        float p0 = __shfl_xor_sync(FULL, v0, 1);
        float p1 = __shfl_xor_sync(FULL, v1, 1);
        float r0 = (d0 & 1) ? p0 : -p0;
        float r1 = (d1 & 1) ? p1 : -p1;
        v0 = v0 * fc0 + r0 * fs0;
        v1 = v1 * fc1 + r1 * fs1;
        g_q[ob + d0] = v0 * 0.125f;
        g_q[ob + d1] = v1 * 0.125f;
    }
    // ---- K ----
    {
        float v0 = base[DIM + d0], v1 = base[DIM + d1];
        float ss = v0 * v0 + v1 * v1;
#pragma unroll
        for (int o = 16; o >= 1; o >>= 1) ss += __shfl_xor_sync(FULL, ss, o);
        float sc = 8.0f / fmaxf(sqrtf(ss), 1e-12f);
        v0 = v0 * sc * kg[d0];
        v1 = v1 * sc * kg[d1];
        float p0 = __shfl_xor_sync(FULL, v0, 1);
        float p1 = __shfl_xor_sync(FULL, v1, 1);
        float r0 = (d0 & 1) ? p0 : -p0;
        float r1 = (d1 & 1) ? p1 : -p1;
        g_k[ob + d0] = v0 * fc0 + r0 * fs0;
        g_k[ob + d1] = v1 * fc1 + r1 * fs1;
    }
    // ---- V (copy) ----
    g_v[ob + d0] = base[2 * DIM + d0];
    g_v[ob + d1] = base[2 * DIM + d1];
}

// ---------------------------------------------------------------------------
// Mask tile nonzero flags (16 x 32 tiles of 128x64)
// ---------------------------------------------------------------------------
__global__ __launch_bounds__(256)
void maskflag_kernel(const float* __restrict__ mask) {
    const int qt = blockIdx.x >> 5;
    const int kt = blockIdx.x & 31;
    int nz = 0;
    for (int u = threadIdx.x; u < 128 * 16; u += 256) {
        int r = u >> 4, c4 = (u & 15) << 2;
        float4 v = *(const float4*)&mask[(size_t)(qt * 128 + r) * SEQ + kt * 64 + c4];
        nz |= (v.x != 0.f) | (v.y != 0.f) | (v.z != 0.f) | (v.w != 0.f);
    }
    nz = __syncthreads_or(nz);
    if (threadIdx.x == 0) g_mflag[blockIdx.x] = nz;
}

// ---------------------------------------------------------------------------
// Flash attention with bf16x3 tensor cores (m16n8k16) + ldmatrix fragments.
// Block = (qt, bh): 128 query rows, 8 warps x 16 rows each; 32 key tiles of 64.
// Hi/lo bf16 split at producer time.  V kept in natural [k][d] layout;
// PV B-fragments loaded via ldmatrix.trans.
// Smem (bf16, stride 72): Qh/Ql 128r, Kh/Kl 64r, Vh/Vl 64r, Ph/Pl 128r.
// ---------------------------------------------------------------------------
#define STR 72
#define QH_OFF 0
#define QL_OFF (QH_OFF + 128*STR)
#define KH_OFF (QL_OFF + 128*STR)
#define KL_OFF (KH_OFF + 64*STR)
#define VH_OFF (KL_OFF + 64*STR)
#define VL_OFF (VH_OFF + 64*STR)
#define PH_OFF (VL_OFF + 64*STR)
#define PL_OFF (PH_OFF + 128*STR)
#define FLASH_SMEM ((PL_OFF + 128*STR) * 2)

__global__ __launch_bounds__(256)
void flash_tc_kernel(const float* __restrict__ mask) {
    extern __shared__ __align__(16) __nv_bfloat16 smb[];
    __nv_bfloat16* Qh = smb + QH_OFF;
    __nv_bfloat16* Ql = smb + QL_OFF;
    __nv_bfloat16* Kh = smb + KH_OFF;
    __nv_bfloat16* Kl = smb + KL_OFF;
    __nv_bfloat16* Vh = smb + VH_OFF;
    __nv_bfloat16* Vl = smb + VL_OFF;
    __nv_bfloat16* Ph = smb + PH_OFF;
    __nv_bfloat16* Pl = smb + PL_OFF;

    const uint32_t sb   = (uint32_t)__cvta_generic_to_shared(smb);
    const uint32_t qh_b = sb + QH_OFF * 2, ql_b = sb + QL_OFF * 2;
    const uint32_t kh_b = sb + KH_OFF * 2, kl_b = sb + KL_OFF * 2;
    const uint32_t vh_b = sb + VH_OFF * 2, vl_b = sb + VL_OFF * 2;
    const uint32_t ph_b = sb + PH_OFF * 2, pl_b = sb + PL_OFF * 2;

    const int qt   = blockIdx.x;    // 0..15
    const int bh   = blockIdx.y;    // 0..31
    const int tid  = threadIdx.x;
    const int lane = tid & 31;
    const int w    = tid >> 5;      // warp 0..7
    const int g    = lane >> 2;     // 0..7
    const int t4   = lane & 3;      // 0..3
    const unsigned FULL = 0xffffffffu;

    const float* qb = g_q + (size_t)bh * SEQ * HD;
    const float* kb = g_k + (size_t)bh * SEQ * HD;
    const float* vb = g_v + (size_t)bh * SEQ * HD;

    // Load Q tile (128x64): split into hi/lo bf16
#pragma unroll
    for (int p = 0; p < 8; p++) {
        int u = tid + p * 256;
        int r = u >> 4, c4 = (u & 15) << 2;
        float4 v = *(const float4*)&qb[(size_t)(qt * 128 + r) * HD + c4];
        uint32_t h0, l0, h1, l1;
        bsplit2(v.x, v.y, h0, l0);
        bsplit2(v.z, v.w, h1, l1);
        U32AT(Qh, r * STR + c4)     = h0;
        U32AT(Qh, r * STR + c4 + 2) = h1;
        U32AT(Ql, r * STR + c4)     = l0;
        U32AT(Ql, r * STR + c4 + 2) = l1;
    }

    const int r0 = 16 * w + g;      // this thread's first q row (local)
    float m0 = -INFINITY, m1 = -INFINITY, l0s = 0.f, l1s = 0.f;
    float4 oacc[8];
#pragma unroll
    for (int dt = 0; dt < 8; dt++) oacc[dt] = make_float4(0.f, 0.f, 0.f, 0.f);

    for (int kt = 0; kt < NKT; kt++) {
        __syncthreads();   // prev iter done with K/V; first iter orders Qh
#pragma unroll
        for (int p = 0; p < 4; p++) {
            int u = tid + p * 256;
            int r = u >> 4, c4 = (u & 15) << 2;           // r = key row, c4 = d
            float4 kv = *(const float4*)&kb[(size_t)(kt * 64 + r) * HD + c4];
            uint32_t h0, l0, h1, l1;
            bsplit2(kv.x, kv.y, h0, l0);
            bsplit2(kv.z, kv.w, h1, l1);
            U32AT(Kh, r * STR + c4)     = h0;
            U32AT(Kh, r * STR + c4 + 2) = h1;
            U32AT(Kl, r * STR + c4)     = l0;
            U32AT(Kl, r * STR + c4 + 2) = l1;
            float4 vv = *(const float4*)&vb[(size_t)(kt * 64 + r) * HD + c4];
            bsplit2(vv.x, vv.y, h0, l0);
            bsplit2(vv.z, vv.w, h1, l1);
            U32AT(Vh, r * STR + c4)     = h0;
            U32AT(Vh, r * STR + c4 + 2) = h1;
            U32AT(Vl, r * STR + c4)     = l0;
            U32AT(Vl, r * STR + c4 + 2) = l1;
        }
        __syncthreads();

        // S = Q K^T : per warp 16x64 via bf16x3 m16n8k16 (4 k-steps over HD=64)
        float4 sacc[8];
#pragma unroll
        for (int nt = 0; nt < 8; nt++) sacc[nt] = make_float4(0.f, 0.f, 0.f, 0.f);
#pragma unroll
        for (int ks = 0; ks < 4; ks++) {
            const int ac = ks * 16;
            uint32_t ah[4], al[4];
            ldsm4(ah, AADDR(qh_b, 16 * w, STR, ac, lane));
            ldsm4(al, AADDR(ql_b, 16 * w, STR, ac, lane));
#pragma unroll
            for (int ntp = 0; ntp < 4; ntp++) {
                int n0 = ntp * 16;
                uint32_t bh4[4], bl4[4];
                ldsm4(bh4, BADDR(kh_b, n0, STR, ac, lane));
                ldsm4(bl4, BADDR(kl_b, n0, STR, ac, lane));
                mma3_bf16(sacc[2 * ntp],     ah, al, bh4,     bl4);
                mma3_bf16(sacc[2 * ntp + 1], ah, al, bh4 + 2, bl4 + 2);
            }
        }
        const int mf = g_mflag[qt * NKT + kt];
        if (mf) {
            const float* mr0 = mask + (size_t)(qt * 128 + r0) * SEQ + kt * 64;
            const float* mr1 = mr0 + 8 * SEQ;
#pragma unroll
            for (int nt = 0; nt < 8; nt++) {
                int c = nt * 8 + 2 * t4;
                float2 a0 = *(const float2*)&mr0[c];
                float2 a1 = *(const float2*)&mr1[c];
                sacc[nt].x += a0.x; sacc[nt].y += a0.y;
                sacc[nt].z += a1.x; sacc[nt].w += a1.y;
            }
        }

        // Online softmax: rows r0 (x,y) and r0+8 (z,w); reduce across 4 lanes.
        float tm0 = -INFINITY, tm1 = -INFINITY;
#pragma unroll
        for (int nt = 0; nt < 8; nt++) {
            tm0 = fmaxf(tm0, fmaxf(sacc[nt].x, sacc[nt].y));
            tm1 = fmaxf(tm1, fmaxf(sacc[nt].z, sacc[nt].w));
        }
#pragma unroll
        for (int o = 1; o < 4; o <<= 1) {
            tm0 = fmaxf(tm0, __shfl_xor_sync(FULL, tm0, o));
            tm1 = fmaxf(tm1, __shfl_xor_sync(FULL, tm1, o));
        }
        float nm0 = fmaxf(m0, tm0), nm1 = fmaxf(m1, tm1);
        float al0 = __expf(m0 - nm0), al1 = __expf(m1 - nm1);
        float rs0 = 0.f, rs1 = 0.f;
#pragma unroll
        for (int nt = 0; nt < 8; nt++) {
            float px = __expf(sacc[nt].x - nm0);
            float py = __expf(sacc[nt].y - nm0);
            float pz = __expf(sacc[nt].z - nm1);
            float pw = __expf(sacc[nt].w - nm1);
            rs0 += px + py; rs1 += pz + pw;
            int c = nt * 8 + 2 * t4;               // adjacent col pair
            uint32_t hp, lp;
            bsplit2(px, py, hp, lp);
            U32AT(Ph, r0 * STR + c) = hp;
            U32AT(Pl, r0 * STR + c) = lp;
            bsplit2(pz, pw, hp, lp);
            U32AT(Ph, (r0 + 8) * STR + c) = hp;
            U32AT(Pl, (r0 + 8) * STR + c) = lp;
        }
#pragma unroll
        for (int o = 1; o < 4; o <<= 1) {
            rs0 += __shfl_xor_sync(FULL, rs0, o);
            rs1 += __shfl_xor_sync(FULL, rs1, o);
        }
        l0s = l0s * al0 + rs0; m0 = nm0;
        l1s = l1s * al1 + rs1; m1 = nm1;
#pragma unroll
        for (int dt = 0; dt < 8; dt++) {
            oacc[dt].x *= al0; oacc[dt].y *= al0;
            oacc[dt].z *= al1; oacc[dt].w *= al1;
        }
        __syncwarp();   // P rows are warp-private; order stores vs ldmatrix

        // O += P V : per warp 16x64 via bf16x3; B frags via ldmatrix.trans
#pragma unroll
        for (int ks = 0; ks < 4; ks++) {
            const int ac = ks * 16;
            uint32_t ah[4], al[4];
            ldsm4(ah, AADDR(ph_b, 16 * w, STR, ac, lane));
            ldsm4(al, AADDR(pl_b, 16 * w, STR, ac, lane));
#pragma unroll
            for (int dtp = 0; dtp < 4; dtp++) {
                int d0 = dtp * 16;
                uint32_t bh4[4], bl4[4];
                ldsm4t(bh4, BTADDR(vh_b, d0, STR, ac, lane));
                ldsm4t(bl4, BTADDR(vl_b, d0, STR, ac, lane));
                mma3_bf16(oacc[2 * dtp],     ah, al, bh4,     bl4);
                mma3_bf16(oacc[2 * dtp + 1], ah, al, bh4 + 2, bl4 + 2);
            }
        }
    }

    // Epilogue: write [b,n,h,d]
    const int b = bh >> 4, h = bh & 15;
    const float inv0 = 1.f / l0s, inv1 = 1.f / l1s;
    const int n0 = qt * 128 + r0;
    const int n1 = n0 + 8;
#pragma unroll
    for (int dt = 0; dt < 8; dt++) {
        int d = dt * 8 + 2 * t4;
        float2 o0 = make_float2(oacc[dt].x * inv0, oacc[dt].y * inv0);
        float2 o1 = make_float2(oacc[dt].z * inv1, oacc[dt].w * inv1);
        *(float2*)&g_ao[(((size_t)(b * SEQ + n0)) * NH + h) * HD + d] = o0;
        *(float2*)&g_ao[(((size_t)(b * SEQ + n1)) * NH + h) * HD + d] = o1;
    }
}

// ---------------------------------------------------------------------------
// Launch
// ---------------------------------------------------------------------------
extern "C" void kernel_launch(void* const* d_in, const int* in_sizes, int n_in,
                              void* d_out, int out_size) {
    const float* x     = (const float*)d_in[0];
    const float* fc    = (const float*)d_in[1];
    const float* fs    = (const float*)d_in[2];
    const float* mask  = (const float*)d_in[3];
    const float* wqkv  = (const float*)d_in[4];
    const float* wproj = (const float*)d_in[5];
    const float* bproj = (const float*)d_in[6];
    const float* qg    = (const float*)d_in[7];
    const float* kg    = (const float*)d_in[8];
    float* out = (float*)d_out;

    float *qkvb, *aob;
    cudaGetSymbolAddress((void**)&qkvb, g_qkv);
    cudaGetSymbolAddress((void**)&aob, g_ao);

    // 1) QKV GEMM: [4096,3072] = x[4096,1024] * wqkv[3072,1024]^T
    {
        dim3 grid(QKVD / 64, TOKENS / 128);
        gemm_bf16x3_nt<<<grid, 256>>>(x, wqkv, qkvb, TOKENS, QKVD, DIM, nullptr);
    }
    // 2) RMSNorm + RoPE + split into [b,h,n,d]
    rmsrope_kernel<<<(Bsz * SEQ * NH) / 8, 256>>>(fc, fs, qg, kg);
    // 3) Mask tile flags (128x64 tiles)
    maskflag_kernel<<<NQT * NKT, 256>>>(mask);
    // 4) Flash attention (bf16x3 tensor cores + ldmatrix)
    {
        cudaFuncSetAttribute(flash_tc_kernel,
                             cudaFuncAttributeMaxDynamicSharedMemorySize, FLASH_SMEM);
        dim3 grid(NQT, Bsz * NH);
        flash_tc_kernel<<<grid, 256, FLASH_SMEM>>>(mask);
    }
    // 5) Output projection: out[4096,1024] = ao * wproj^T + bproj
    {
        dim3 grid(DIM / 64, TOKENS / 128);
        gemm_bf16x3_nt<<<grid, 256>>>(aob, wproj, out, TOKENS, DIM, DIM, bproj);
    }
}

// round 15
// speedup vs baseline: 3.8760x; 1.0414x over previous
#include <cuda_runtime.h>
#include <cuda_bf16.h>
#include <math.h>
#include <stdint.h>

// Problem constants
#define Bsz   2
#define SEQ   2048
#define DIM   1024
#define NH    16
#define HD    64
#define TOKENS (Bsz*SEQ)     // 4096
#define QKVD   (3*DIM)       // 3072
#define NKT   (SEQ/64)       // 32 key tiles of 64
#define NQT   (SEQ/128)      // 16 query tiles of 128

// ---------------------------------------------------------------------------
// Scratch (device globals; no allocations allowed)
// ---------------------------------------------------------------------------
__device__ float g_qkv[TOKENS * QKVD];          // [b,n, t,h,d]
__device__ float g_q[Bsz * NH * SEQ * HD];      // [b,h,n,d] (pre-scaled)
__device__ float g_k[Bsz * NH * SEQ * HD];
__device__ float g_v[Bsz * NH * SEQ * HD];
__device__ float g_ao[TOKENS * DIM];            // [b,n,h,d] = [b,n,c]
__device__ int   g_mflag[NQT * NKT];            // per 128x64 mask tile: nonzero?

// ---------------------------------------------------------------------------
// bf16x3 helpers: x = hi + lo, each bf16; D += Ah*Bh + Al*Bh + Ah*Bl
// ---------------------------------------------------------------------------
__device__ __forceinline__ void bsplit2(float e0, float e1, uint32_t& hp, uint32_t& lp) {
    __nv_bfloat16 h0 = __float2bfloat16_rn(e0);
    __nv_bfloat16 h1 = __float2bfloat16_rn(e1);
    float r0 = e0 - __bfloat162float(h0);
    float r1 = e1 - __bfloat162float(h1);
    __nv_bfloat16 l0 = __float2bfloat16_rn(r0);
    __nv_bfloat16 l1 = __float2bfloat16_rn(r1);
    hp = (uint32_t)__bfloat16_as_ushort(h0) | ((uint32_t)__bfloat16_as_ushort(h1) << 16);
    lp = (uint32_t)__bfloat16_as_ushort(l0) | ((uint32_t)__bfloat16_as_ushort(l1) << 16);
}

__device__ __forceinline__ void mma_bf16(float4& d, const uint32_t a[4], const uint32_t b[2]) {
    asm volatile(
        "mma.sync.aligned.m16n8k16.row.col.f32.bf16.bf16.f32 "
        "{%0,%1,%2,%3}, {%4,%5,%6,%7}, {%8,%9}, {%0,%1,%2,%3};\n"
        : "+f"(d.x), "+f"(d.y), "+f"(d.z), "+f"(d.w)
        : "r"(a[0]), "r"(a[1]), "r"(a[2]), "r"(a[3]), "r"(b[0]), "r"(b[1]));
}

__device__ __forceinline__ void mma3_bf16(float4& d,
                                          const uint32_t ah[4], const uint32_t al[4],
                                          const uint32_t bh[2], const uint32_t bl[2]) {
    mma_bf16(d, ah, bh);
    mma_bf16(d, al, bh);
    mma_bf16(d, ah, bl);
}

__device__ __forceinline__ void ldsm4(uint32_t r[4], uint32_t a) {
    asm volatile("ldmatrix.sync.aligned.m8n8.x4.shared.b16 {%0,%1,%2,%3}, [%4];"
                 : "=r"(r[0]), "=r"(r[1]), "=r"(r[2]), "=r"(r[3]) : "r"(a));
}
__device__ __forceinline__ void ldsm4t(uint32_t r[4], uint32_t a) {
    asm volatile("ldmatrix.sync.aligned.m8n8.x4.trans.shared.b16 {%0,%1,%2,%3}, [%4];"
                 : "=r"(r[0]), "=r"(r[1]), "=r"(r[2]), "=r"(r[3]) : "r"(a));
}

// A-fragment (16x16) address: rows row0..+15 (lane&15), col ac + (lane>>4)*8
#define AADDR(base_b, row0, stride, ac, lane) \
    ((base_b) + ((((row0) + ((lane) & 15)) * (stride) + (ac) + (((lane) >> 4) << 3)) << 1))
// B-fragment pair (two n8k16 tiles at n0, n0+8): rows n, k-halves interleaved
#define BADDR(base_b, n0, stride, ac, lane) \
    ((base_b) + ((((n0) + (((lane) >> 4) << 3) + ((lane) & 7)) * (stride) + (ac) + ((((lane) >> 3) & 1) << 3)) << 1))
// Transposed B-fragment pair from natural [k][d] layout: rows k, cols d0/d0+8
#define BTADDR(base_b, d0, stride, ac, lane) \
    ((base_b) + ((((ac) + ((((lane) >> 3) & 1) << 3) + ((lane) & 7)) * (stride) + (d0) + (((lane) >> 4) << 3)) << 1))

// u32 view of a bf16 smem location (index must be even)
#define U32AT(base, idx) (*(uint32_t*)((base) + (idx)))

// ---------------------------------------------------------------------------
// bf16x3 NT GEMM: C[M,N] = A[M,K] * B[N,K]^T (+ bias[N])
// BM=128, BN=64, BK=32; 256 threads = 8 warps (4 M x 2 N), warp tile 32x32.
// Double-buffered smem, register prefetch, one sync per k-step.
// ---------------------------------------------------------------------------
#define GST  40                       // bf16 row stride for GEMM tiles
#define GBUF (2*128*GST + 2*64*GST)   // bf16 per buffer = 15360
#define GAH 0
#define GAL (128*GST)
#define GBH (2*128*GST)
#define GBL (2*128*GST + 64*GST)

__global__ __launch_bounds__(256, 2)
void gemm_bf16x3_nt(const float* __restrict__ A, const float* __restrict__ B,
                    float* __restrict__ C, int M, int Nn, int K,
                    const float* __restrict__ bias) {
    __shared__ __align__(16) __nv_bfloat16 gsm[2 * GBUF];

    const int tid  = threadIdx.x;
    const int lane = tid & 31;
    const int w    = tid >> 5;
    const int wm   = w & 3;          // warp M index (0..3)
    const int wn   = w >> 2;         // warp N index (0..1)
    const int g    = lane >> 2;      // 0..7
    const int t4   = lane & 3;       // 0..3
    const int bm   = blockIdx.y * 128;
    const int bn   = blockIdx.x * 64;

    const uint32_t gsm_b = (uint32_t)__cvta_generic_to_shared(gsm);

    const int lr  = tid >> 3;        // 0..31
    const int lc4 = (tid & 7) << 2;  // 0,4,...,28

    float4 areg[4], breg[2];

    auto LOADAB = [&](int k0) {
#pragma unroll
        for (int p = 0; p < 4; p++)
            areg[p] = *(const float4*)&A[(size_t)(bm + p * 32 + lr) * K + k0 + lc4];
#pragma unroll
        for (int p = 0; p < 2; p++)
            breg[p] = *(const float4*)&B[(size_t)(bn + p * 32 + lr) * K + k0 + lc4];
    };
    auto STOREAB = [&](int bb) {
        __nv_bfloat16* Ah = gsm + bb * GBUF + GAH;
        __nv_bfloat16* Al = gsm + bb * GBUF + GAL;
        __nv_bfloat16* Bh = gsm + bb * GBUF + GBH;
        __nv_bfloat16* Bl = gsm + bb * GBUF + GBL;
#pragma unroll
        for (int p = 0; p < 4; p++) {
            int row = p * 32 + lr;
            uint32_t h0, l0, h1, l1;
            bsplit2(areg[p].x, areg[p].y, h0, l0);
            bsplit2(areg[p].z, areg[p].w, h1, l1);
            U32AT(Ah, row * GST + lc4)     = h0;
            U32AT(Ah, row * GST + lc4 + 2) = h1;
            U32AT(Al, row * GST + lc4)     = l0;
            U32AT(Al, row * GST + lc4 + 2) = l1;
        }
#pragma unroll
        for (int p = 0; p < 2; p++) {
            int row = p * 32 + lr;
            uint32_t h0, l0, h1, l1;
            bsplit2(breg[p].x, breg[p].y, h0, l0);
            bsplit2(breg[p].z, breg[p].w, h1, l1);
            U32AT(Bh, row * GST + lc4)     = h0;
            U32AT(Bh, row * GST + lc4 + 2) = h1;
            U32AT(Bl, row * GST + lc4)     = l0;
            U32AT(Bl, row * GST + lc4 + 2) = l1;
        }
    };

    float4 acc[2][4];
#pragma unroll
    for (int i = 0; i < 2; i++)
#pragma unroll
        for (int j = 0; j < 4; j++) acc[i][j] = make_float4(0.f, 0.f, 0.f, 0.f);

    LOADAB(0);
    STOREAB(0);
    __syncthreads();

    const int NIT = K / 32;
    for (int it = 0; it < NIT; it++) {
        const int bb = it & 1;
        if (it + 1 < NIT) LOADAB((it + 1) * 32);

        const uint32_t gb    = gsm_b + bb * GBUF * 2;
        const uint32_t ash_b = gb + GAH * 2, asl_b = gb + GAL * 2;
        const uint32_t bsh_b = gb + GBH * 2, bsl_b = gb + GBL * 2;

#pragma unroll
        for (int ks = 0; ks < 2; ks++) {
            const int ac = ks * 16;
            uint32_t ah[2][4], al[2][4];
#pragma unroll
            for (int mt = 0; mt < 2; mt++) {
                int ar = wm * 32 + mt * 16;
                ldsm4(ah[mt], AADDR(ash_b, ar, GST, ac, lane));
                ldsm4(al[mt], AADDR(asl_b, ar, GST, ac, lane));
            }
#pragma unroll
            for (int ntp = 0; ntp < 2; ntp++) {
                int n0 = wn * 32 + ntp * 16;
                uint32_t bh4[4], bl4[4];
                ldsm4(bh4, BADDR(bsh_b, n0, GST, ac, lane));
                ldsm4(bl4, BADDR(bsl_b, n0, GST, ac, lane));
#pragma unroll
                for (int mt = 0; mt < 2; mt++) {
                    mma3_bf16(acc[mt][2 * ntp],     ah[mt], al[mt], bh4,     bl4);
                    mma3_bf16(acc[mt][2 * ntp + 1], ah[mt], al[mt], bh4 + 2, bl4 + 2);
                }
            }
        }

        if (it + 1 < NIT) STOREAB(bb ^ 1);
        __syncthreads();
    }

#pragma unroll
    for (int mt = 0; mt < 2; mt++) {
#pragma unroll
        for (int nt = 0; nt < 4; nt++) {
            int row = bm + wm * 32 + mt * 16 + g;
            int col = bn + wn * 32 + nt * 8 + 2 * t4;
            float bx = 0.f, by = 0.f;
            if (bias) { bx = bias[col]; by = bias[col + 1]; }
            float2 o0 = make_float2(acc[mt][nt].x + bx, acc[mt][nt].y + by);
            float2 o1 = make_float2(acc[mt][nt].z + bx, acc[mt][nt].w + by);
            *(float2*)&C[(size_t)row * Nn + col] = o0;
            *(float2*)&C[(size_t)(row + 8) * Nn + col] = o1;
        }
    }
}

// ---------------------------------------------------------------------------
// RMSNorm + RoPE + head split.  One warp per (b,n,h); 2 elems/lane (d, d+32).
// ---------------------------------------------------------------------------
__global__ __launch_bounds__(256)
void rmsrope_kernel(const float* __restrict__ fc, const float* __restrict__ fs,
                    const float* __restrict__ qg, const float* __restrict__ kg) {
    const int gw   = (blockIdx.x * blockDim.x + threadIdx.x) >> 5;
    const int lane = threadIdx.x & 31;
    const int h = gw & (NH - 1);
    const int n = (gw >> 4) & (SEQ - 1);
    const int b = gw >> 15;

    const float* base = g_qkv + (size_t)(b * SEQ + n) * QKVD + h * HD;
    const int d0 = lane, d1 = lane + 32;

    const size_t fbase = (size_t)(b * SEQ + n) * HD;
    const float fc0 = fc[fbase + d0], fc1 = fc[fbase + d1];
    const float fs0 = fs[fbase + d0], fs1 = fs[fbase + d1];

    const size_t ob = ((size_t)(b * NH + h) * SEQ + n) * HD;
    const unsigned FULL = 0xffffffffu;

    // ---- Q ----
    {
        float v0 = base[d0], v1 = base[d1];
        float ss = v0 * v0 + v1 * v1;
#pragma unroll
        for (int o = 16; o >= 1; o >>= 1) ss += __shfl_xor_sync(FULL, ss, o);
        float sc = 8.0f / fmaxf(sqrtf(ss), 1e-12f);
        v0 = v0 * sc * qg[d0];
        v1 = v1 * sc * qg[d1];
        float p0 = __shfl_xor_sync(FULL, v0, 1);
        float p1 = __shfl_xor_sync(FULL, v1, 1);
        float r0 = (d0 & 1) ? p0 : -p0;
        float r1 = (d1 & 1) ? p1 : -p1;
        v0 = v0 * fc0 + r0 * fs0;
        v1 = v1 * fc1 + r1 * fs1;
        g_q[ob + d0] = v0 * 0.125f;
        g_q[ob + d1] = v1 * 0.125f;
    }
    // ---- K ----
    {
        float v0 = base[DIM + d0], v1 = base[DIM + d1];
        float ss = v0 * v0 + v1 * v1;
#pragma unroll
        for (int o = 16; o >= 1; o >>= 1) ss += __shfl_xor_sync(FULL, ss, o);
        float sc = 8.0f / fmaxf(sqrtf(ss), 1e-12f);
        v0 = v0 * sc * kg[d0];
        v1 = v1 * sc * kg[d1];
        float p0 = __shfl_xor_sync(FULL, v0, 1);
        float p1 = __shfl_xor_sync(FULL, v1, 1);
        float r0 = (d0 & 1) ? p0 : -p0;
        float r1 = (d1 & 1) ? p1 : -p1;
        g_k[ob + d0] = v0 * fc0 + r0 * fs0;
        g_k[ob + d1] = v1 * fc1 + r1 * fs1;
    }
    // ---- V (copy) ----
    g_v[ob + d0] = base[2 * DIM + d0];
    g_v[ob + d1] = base[2 * DIM + d1];
}

// ---------------------------------------------------------------------------
// Mask tile nonzero flags (16 x 32 tiles of 128x64)
// ---------------------------------------------------------------------------
__global__ __launch_bounds__(256)
void maskflag_kernel(const float* __restrict__ mask) {
    const int qt = blockIdx.x >> 5;
    const int kt = blockIdx.x & 31;
    int nz = 0;
    for (int u = threadIdx.x; u < 128 * 16; u += 256) {
        int r = u >> 4, c4 = (u & 15) << 2;
        float4 v = *(const float4*)&mask[(size_t)(qt * 128 + r) * SEQ + kt * 64 + c4];
        nz |= (v.x != 0.f) | (v.y != 0.f) | (v.z != 0.f) | (v.w != 0.f);
    }
    nz = __syncthreads_or(nz);
    if (threadIdx.x == 0) g_mflag[blockIdx.x] = nz;
}

// ---------------------------------------------------------------------------
// Flash attention, bf16x3 + ldmatrix, register-resident P, double-buffered
// K/V with register prefetch (one __syncthreads per key tile).
// Block = (qt, bh): 128 query rows, 8 warps x 16 rows; 32 key tiles of 64.
// Smem (bf16, stride 72): Qh/Ql 128r + 2 x [Kh/Kl/Vh/Vl 64r] = 110592 B.
// ---------------------------------------------------------------------------
#define STR 72
#define QH_OFF 0
#define QL_OFF (128*STR)
#define KV_OFF (2*128*STR)
#define KVBUF  (4*64*STR)
#define FLASH_SMEM ((2*128*STR + 2*KVBUF) * 2)

__global__ __launch_bounds__(256, 2)
void flash_tc_kernel(const float* __restrict__ mask) {
    extern __shared__ __align__(16) __nv_bfloat16 smb[];
    __nv_bfloat16* Qh = smb + QH_OFF;
    __nv_bfloat16* Ql = smb + QL_OFF;

    const uint32_t sb   = (uint32_t)__cvta_generic_to_shared(smb);
    const uint32_t qh_b = sb + QH_OFF * 2, ql_b = sb + QL_OFF * 2;

    const int qt   = blockIdx.x;    // 0..15
    const int bh   = blockIdx.y;    // 0..31
    const int tid  = threadIdx.x;
    const int lane = tid & 31;
    const int w    = tid >> 5;      // warp 0..7
    const int g    = lane >> 2;     // 0..7
    const int t4   = lane & 3;      // 0..3
    const unsigned FULL = 0xffffffffu;

    const float* qb = g_q + (size_t)bh * SEQ * HD;
    const float* kb = g_k + (size_t)bh * SEQ * HD;
    const float* vb = g_v + (size_t)bh * SEQ * HD;

    // Load Q tile (128x64): split into hi/lo bf16
#pragma unroll
    for (int p = 0; p < 8; p++) {
        int u = tid + p * 256;
        int r = u >> 4, c4 = (u & 15) << 2;
        float4 v = *(const float4*)&qb[(size_t)(qt * 128 + r) * HD + c4];
        uint32_t h0, l0, h1, l1;
        bsplit2(v.x, v.y, h0, l0);
        bsplit2(v.z, v.w, h1, l1);
        U32AT(Qh, r * STR + c4)     = h0;
        U32AT(Qh, r * STR + c4 + 2) = h1;
        U32AT(Ql, r * STR + c4)     = l0;
        U32AT(Ql, r * STR + c4 + 2) = l1;
    }

    float4 kreg[4], vreg[4];
    auto LOADKV = [&](int kt) {
#pragma unroll
        for (int p = 0; p < 4; p++) {
            int u = tid + p * 256;
            int r = u >> 4, c4 = (u & 15) << 2;
            kreg[p] = *(const float4*)&kb[(size_t)(kt * 64 + r) * HD + c4];
            vreg[p] = *(const float4*)&vb[(size_t)(kt * 64 + r) * HD + c4];
        }
    };
    auto STOREKV = [&](int bb) {
        __nv_bfloat16* Kh = smb + KV_OFF + bb * KVBUF;
        __nv_bfloat16* Kl = Kh + 64 * STR;
        __nv_bfloat16* Vh = Kh + 2 * 64 * STR;
        __nv_bfloat16* Vl = Kh + 3 * 64 * STR;
#pragma unroll
        for (int p = 0; p < 4; p++) {
            int u = tid + p * 256;
            int r = u >> 4, c4 = (u & 15) << 2;
            uint32_t h0, l0, h1, l1;
            bsplit2(kreg[p].x, kreg[p].y, h0, l0);
            bsplit2(kreg[p].z, kreg[p].w, h1, l1);
            U32AT(Kh, r * STR + c4)     = h0;
            U32AT(Kh, r * STR + c4 + 2) = h1;
            U32AT(Kl, r * STR + c4)     = l0;
            U32AT(Kl, r * STR + c4 + 2) = l1;
            bsplit2(vreg[p].x, vreg[p].y, h0, l0);
            bsplit2(vreg[p].z, vreg[p].w, h1, l1);
            U32AT(Vh, r * STR + c4)     = h0;
            U32AT(Vh, r * STR + c4 + 2) = h1;
            U32AT(Vl, r * STR + c4)     = l0;
            U32AT(Vl, r * STR + c4 + 2) = l1;
        }
    };

    const int r0 = 16 * w + g;      // this thread's first q row (local)
    float m0 = -INFINITY, m1 = -INFINITY, l0s = 0.f, l1s = 0.f;
    float4 oacc[8];
#pragma unroll
    for (int dt = 0; dt < 8; dt++) oacc[dt] = make_float4(0.f, 0.f, 0.f, 0.f);

    // Prologue: tile 0 into buffer 0 (also publishes Q)
    LOADKV(0);
    STOREKV(0);
    __syncthreads();

    for (int kt = 0; kt < NKT; kt++) {
        const int bb = kt & 1;
        if (kt + 1 < NKT) LOADKV(kt + 1);     // prefetch; consumed after compute

        const uint32_t kvb  = sb + (KV_OFF + bb * KVBUF) * 2;
        const uint32_t kh_b = kvb;
        const uint32_t kl_b = kvb + (64 * STR) * 2;
        const uint32_t vh_b = kvb + (2 * 64 * STR) * 2;
        const uint32_t vl_b = kvb + (3 * 64 * STR) * 2;

        // S = Q K^T : per warp 16x64 via bf16x3 m16n8k16 (4 k-steps over HD=64)
        float4 sacc[8];
#pragma unroll
        for (int nt = 0; nt < 8; nt++) sacc[nt] = make_float4(0.f, 0.f, 0.f, 0.f);
#pragma unroll
        for (int ks = 0; ks < 4; ks++) {
            const int ac = ks * 16;
            uint32_t ah[4], al[4];
            ldsm4(ah, AADDR(qh_b, 16 * w, STR, ac, lane));
            ldsm4(al, AADDR(ql_b, 16 * w, STR, ac, lane));
#pragma unroll
            for (int ntp = 0; ntp < 4; ntp++) {
                int n0 = ntp * 16;
                uint32_t bh4[4], bl4[4];
                ldsm4(bh4, BADDR(kh_b, n0, STR, ac, lane));
                ldsm4(bl4, BADDR(kl_b, n0, STR, ac, lane));
                mma3_bf16(sacc[2 * ntp],     ah, al, bh4,     bl4);
                mma3_bf16(sacc[2 * ntp + 1], ah, al, bh4 + 2, bl4 + 2);
            }
        }
        const int mf = g_mflag[qt * NKT + kt];
        if (mf) {
            const float* mr0 = mask + (size_t)(qt * 128 + r0) * SEQ + kt * 64;
            const float* mr1 = mr0 + 8 * SEQ;
#pragma unroll
            for (int nt = 0; nt < 8; nt++) {
                int c = nt * 8 + 2 * t4;
                float2 a0 = *(const float2*)&mr0[c];
                float2 a1 = *(const float2*)&mr1[c];
                sacc[nt].x += a0.x; sacc[nt].y += a0.y;
                sacc[nt].z += a1.x; sacc[nt].w += a1.y;
            }
        }

        // Online softmax: rows r0 (x,y) and r0+8 (z,w); reduce across 4 lanes.
        float tm0 = -INFINITY, tm1 = -INFINITY;
#pragma unroll
        for (int nt = 0; nt < 8; nt++) {
            tm0 = fmaxf(tm0, fmaxf(sacc[nt].x, sacc[nt].y));
            tm1 = fmaxf(tm1, fmaxf(sacc[nt].z, sacc[nt].w));
        }
#pragma unroll
        for (int o = 1; o < 4; o <<= 1) {
            tm0 = fmaxf(tm0, __shfl_xor_sync(FULL, tm0, o));
            tm1 = fmaxf(tm1, __shfl_xor_sync(FULL, tm1, o));
        }
        float nm0 = fmaxf(m0, tm0), nm1 = fmaxf(m1, tm1);
        float al0 = __expf(m0 - nm0), al1 = __expf(m1 - nm1);
        float rs0 = 0.f, rs1 = 0.f;
#pragma unroll
        for (int nt = 0; nt < 8; nt++) {
            sacc[nt].x = __expf(sacc[nt].x - nm0);
            sacc[nt].y = __expf(sacc[nt].y - nm0);
            sacc[nt].z = __expf(sacc[nt].z - nm1);
            sacc[nt].w = __expf(sacc[nt].w - nm1);
            rs0 += sacc[nt].x + sacc[nt].y;
            rs1 += sacc[nt].z + sacc[nt].w;
        }
#pragma unroll
        for (int o = 1; o < 4; o <<= 1) {
            rs0 += __shfl_xor_sync(FULL, rs0, o);
            rs1 += __shfl_xor_sync(FULL, rs1, o);
        }
        l0s = l0s * al0 + rs0; m0 = nm0;
        l1s = l1s * al1 + rs1; m1 = nm1;
#pragma unroll
        for (int dt = 0; dt < 8; dt++) {
            oacc[dt].x *= al0; oacc[dt].y *= al0;
            oacc[dt].z *= al1; oacc[dt].w *= al1;
        }

        // O += P V : P A-fragments built in registers from sacc (C-frag == A-frag
        // layout); V B-fragments via ldmatrix.trans from natural [k][d] smem.
#pragma unroll
        for (int ks = 0; ks < 4; ks++) {
            const int ac = ks * 16;
            uint32_t ah[4], al[4];
            bsplit2(sacc[2 * ks].x,     sacc[2 * ks].y,     ah[0], al[0]);
            bsplit2(sacc[2 * ks].z,     sacc[2 * ks].w,     ah[1], al[1]);
            bsplit2(sacc[2 * ks + 1].x, sacc[2 * ks + 1].y, ah[2], al[2]);
            bsplit2(sacc[2 * ks + 1].z, sacc[2 * ks + 1].w, ah[3], al[3]);
#pragma unroll
            for (int dtp = 0; dtp < 4; dtp++) {
                int d0 = dtp * 16;
                uint32_t bh4[4], bl4[4];
                ldsm4t(bh4, BTADDR(vh_b, d0, STR, ac, lane));
                ldsm4t(bl4, BTADDR(vl_b, d0, STR, ac, lane));
                mma3_bf16(oacc[2 * dtp],     ah, al, bh4,     bl4);
                mma3_bf16(oacc[2 * dtp + 1], ah, al, bh4 + 2, bl4 + 2);
            }
        }

        if (kt + 1 < NKT) STOREKV(bb ^ 1);    // fill other buffer (no one reads it yet)
        __syncthreads();                      // publish buffer; K/V reads of bb done
    }

    // Epilogue: write [b,n,h,d]
    const int b = bh >> 4, h = bh & 15;
    const float inv0 = 1.f / l0s, inv1 = 1.f / l1s;
    const int n0 = qt * 128 + r0;
    const int n1 = n0 + 8;
#pragma unroll
    for (int dt = 0; dt < 8; dt++) {
        int d = dt * 8 + 2 * t4;
        float2 o0 = make_float2(oacc[dt].x * inv0, oacc[dt].y * inv0);
        float2 o1 = make_float2(oacc[dt].z * inv1, oacc[dt].w * inv1);
        *(float2*)&g_ao[(((size_t)(b * SEQ + n0)) * NH + h) * HD + d] = o0;
        *(float2*)&g_ao[(((size_t)(b * SEQ + n1)) * NH + h) * HD + d] = o1;
    }
}

// ---------------------------------------------------------------------------
// Launch
// ---------------------------------------------------------------------------
extern "C" void kernel_launch(void* const* d_in, const int* in_sizes, int n_in,
                              void* d_out, int out_size) {
    const float* x     = (const float*)d_in[0];
    const float* fc    = (const float*)d_in[1];
    const float* fs    = (const float*)d_in[2];
    const float* mask  = (const float*)d_in[3];
    const float* wqkv  = (const float*)d_in[4];
    const float* wproj = (const float*)d_in[5];
    const float* bproj = (const float*)d_in[6];
    const float* qg    = (const float*)d_in[7];
    const float* kg    = (const float*)d_in[8];
    float* out = (float*)d_out;

    float *qkvb, *aob;
    cudaGetSymbolAddress((void**)&qkvb, g_qkv);
    cudaGetSymbolAddress((void**)&aob, g_ao);

    // 1) QKV GEMM: [4096,3072] = x[4096,1024] * wqkv[3072,1024]^T
    {
        dim3 grid(QKVD / 64, TOKENS / 128);
        gemm_bf16x3_nt<<<grid, 256>>>(x, wqkv, qkvb, TOKENS, QKVD, DIM, nullptr);
    }
    // 2) RMSNorm + RoPE + split into [b,h,n,d]
    rmsrope_kernel<<<(Bsz * SEQ * NH) / 8, 256>>>(fc, fs, qg, kg);
    // 3) Mask tile flags (128x64 tiles)
    maskflag_kernel<<<NQT * NKT, 256>>>(mask);
    // 4) Flash attention (bf16x3, ldmatrix, reg-P, double-buffered K/V)
    {
        cudaFuncSetAttribute(flash_tc_kernel,
                             cudaFuncAttributeMaxDynamicSharedMemorySize, FLASH_SMEM);
        dim3 grid(NQT, Bsz * NH);
        flash_tc_kernel<<<grid, 256, FLASH_SMEM>>>(mask);
    }
    // 5) Output projection: out[4096,1024] = ao * wproj^T + bproj
    {
        dim3 grid(DIM / 64, TOKENS / 128);
        gemm_bf16x3_nt<<<grid, 256>>>(aob, wproj, out, TOKENS, DIM, DIM, bproj);
    }
}